// round 1
// baseline (speedup 1.0000x reference)
#include <cuda_runtime.h>
#include <math.h>
#include <stdint.h>

// ---------------- Problem constants ----------------
#define N_NODES 12288
#define B_BATCH 64
#define R_REG   36
#define E_EDGES 196608
#define DIN     512
#define DOUT    512
#define PDIM    256
#define DIMG    1024
#define BR      (B_BATCH * R_REG)   // 2304

// ---------------- Scratch (device globals; no allocation allowed) ----------------
__device__ __align__(16) float g_img_proj[BR * PDIM];       // img_feats @ Wi + bi
__device__ __align__(16) float g_img_fc[BR * DOUT];         // img_feats @ Wim
__device__ __align__(16) float g_node_proj[N_NODES * PDIM]; // h @ Wf + bf
__device__ __align__(16) float g_h1[N_NODES * DOUT];        // h @ Wn + bn
__device__ __align__(16) float g_msg[N_NODES * DOUT];       // bim + att*img_fc + neigh
__device__ int g_deg[N_NODES];
__device__ int g_cursor[N_NODES];
__device__ int g_off[N_NODES + 1];
__device__ int g_csr_src[E_EDGES];

// ---------------- Generic 128x128x8 fp32 SGEMM, 256 threads, 8x8 microtile ----------------
// All M,N,K used here are exact multiples of the tile sizes -> no bounds checks.
__global__ __launch_bounds__(256) void sgemm_kernel(
    const float* __restrict__ A, const float* __restrict__ B,
    const float* __restrict__ bias, float* __restrict__ C,
    int M, int N, int K, int do_relu)
{
    __shared__ float As[8][128];
    __shared__ float Bs[8][128];

    const int tid = threadIdx.x;
    const int bx = blockIdx.x, by = blockIdx.y;
    const int tx = tid & 15, ty = tid >> 4;

    const int aRow = tid >> 1;        // 0..127
    const int aK   = (tid & 1) * 4;   // 0 or 4
    const int bRow = tid >> 5;        // 0..7
    const int bCol = (tid & 31) * 4;  // 0..124

    const float* Aptr = A + (size_t)(by * 128 + aRow) * K + aK;
    const float* Bptr = B + (size_t)bRow * N + bx * 128 + bCol;

    float acc[8][8];
    #pragma unroll
    for (int i = 0; i < 8; i++)
        #pragma unroll
        for (int j = 0; j < 8; j++) acc[i][j] = 0.0f;

    for (int k0 = 0; k0 < K; k0 += 8) {
        float4 a = *(const float4*)(Aptr + k0);
        float4 b = *(const float4*)(Bptr + (size_t)k0 * N);
        As[aK + 0][aRow] = a.x;
        As[aK + 1][aRow] = a.y;
        As[aK + 2][aRow] = a.z;
        As[aK + 3][aRow] = a.w;
        *(float4*)&Bs[bRow][bCol] = b;
        __syncthreads();
        #pragma unroll
        for (int k = 0; k < 8; k++) {
            float ra[8], rb[8];
            #pragma unroll
            for (int i = 0; i < 8; i++) ra[i] = As[k][ty * 8 + i];
            #pragma unroll
            for (int j = 0; j < 8; j++) rb[j] = Bs[k][tx * 8 + j];
            #pragma unroll
            for (int i = 0; i < 8; i++)
                #pragma unroll
                for (int j = 0; j < 8; j++) acc[i][j] += ra[i] * rb[j];
        }
        __syncthreads();
    }

    #pragma unroll
    for (int i = 0; i < 8; i++) {
        int row = by * 128 + ty * 8 + i;
        #pragma unroll
        for (int j = 0; j < 8; j++) {
            int col = bx * 128 + tx * 8 + j;
            float v = acc[i][j] + (bias ? bias[col] : 0.0f);
            if (do_relu) v = fmaxf(v, 0.0f);
            C[(size_t)row * N + col] = v;
        }
    }
}

// ---------------- Final GEMM: out = relu([msg | h1] @ Wap + bap), K=1024 split 512/512 ----------------
__global__ __launch_bounds__(256) void sgemm_cat_kernel(
    const float* __restrict__ Wap, const float* __restrict__ bap,
    float* __restrict__ out)
{
    const int N = DOUT;  // 512
    __shared__ float As[8][128];
    __shared__ float Bs[8][128];

    const int tid = threadIdx.x;
    const int bx = blockIdx.x, by = blockIdx.y;
    const int tx = tid & 15, ty = tid >> 4;

    const int aRow = tid >> 1;
    const int aK   = (tid & 1) * 4;
    const int bRow = tid >> 5;
    const int bCol = (tid & 31) * 4;

    const int row = by * 128 + aRow;
    const float* Bptr = Wap + (size_t)bRow * N + bx * 128 + bCol;

    float acc[8][8];
    #pragma unroll
    for (int i = 0; i < 8; i++)
        #pragma unroll
        for (int j = 0; j < 8; j++) acc[i][j] = 0.0f;

    for (int k0 = 0; k0 < 1024; k0 += 8) {
        int kg = k0 + aK;
        float4 a = (kg < 512)
            ? *(const float4*)(g_msg + (size_t)row * 512 + kg)
            : *(const float4*)(g_h1  + (size_t)row * 512 + (kg - 512));
        float4 b = *(const float4*)(Bptr + (size_t)k0 * N);
        As[aK + 0][aRow] = a.x;
        As[aK + 1][aRow] = a.y;
        As[aK + 2][aRow] = a.z;
        As[aK + 3][aRow] = a.w;
        *(float4*)&Bs[bRow][bCol] = b;
        __syncthreads();
        #pragma unroll
        for (int k = 0; k < 8; k++) {
            float ra[8], rb[8];
            #pragma unroll
            for (int i = 0; i < 8; i++) ra[i] = As[k][ty * 8 + i];
            #pragma unroll
            for (int j = 0; j < 8; j++) rb[j] = Bs[k][tx * 8 + j];
            #pragma unroll
            for (int i = 0; i < 8; i++)
                #pragma unroll
                for (int j = 0; j < 8; j++) acc[i][j] += ra[i] * rb[j];
        }
        __syncthreads();
    }

    #pragma unroll
    for (int i = 0; i < 8; i++) {
        int r = by * 128 + ty * 8 + i;
        #pragma unroll
        for (int j = 0; j < 8; j++) {
            int c = bx * 128 + tx * 8 + j;
            float v = fmaxf(acc[i][j] + bap[c], 0.0f);
            out[(size_t)r * N + c] = v;
        }
    }
}

// ---------------- Attention + image message (per node) ----------------
// msg[n,:] = bim + sum_r softmax_r(Wa . tanh(node_proj[n] + img_proj[b,r]) + ba) * img_fc[b,r,:]
__global__ __launch_bounds__(256) void att_kernel(
    const int* __restrict__ batch_ids,
    const float* __restrict__ Wa, const float* __restrict__ ba,
    const float* __restrict__ bim)
{
    const int n = blockIdx.x;
    const int tid = threadIdx.x;        // 256
    const int lane = tid & 31, warp = tid >> 5;

    __shared__ float np[PDIM];
    __shared__ float wa[PDIM];
    __shared__ float sl[40];            // logits then att

    const int b = batch_ids[n];
    np[tid] = g_node_proj[(size_t)n * PDIM + tid];
    wa[tid] = Wa[tid];
    __syncthreads();

    // logits: warp w handles r = w, w+8, ...
    for (int r = warp; r < R_REG; r += 8) {
        const float* ip = g_img_proj + (size_t)(b * R_REG + r) * PDIM;
        float part = 0.0f;
        #pragma unroll
        for (int i = 0; i < 8; i++) {
            int p = lane + 32 * i;
            part += tanhf(np[p] + ip[p]) * wa[p];
        }
        #pragma unroll
        for (int o = 16; o > 0; o >>= 1) part += __shfl_xor_sync(0xffffffffu, part, o);
        if (lane == 0) sl[r] = part + ba[0];
    }
    __syncthreads();

    // softmax over 36 (warp 0)
    if (warp == 0) {
        float v0 = sl[lane];
        float v1 = (lane < 4) ? sl[32 + lane] : -INFINITY;
        float m = fmaxf(v0, v1);
        #pragma unroll
        for (int o = 16; o > 0; o >>= 1) m = fmaxf(m, __shfl_xor_sync(0xffffffffu, m, o));
        float e0 = __expf(v0 - m);
        float e1 = (lane < 4) ? __expf(v1 - m) : 0.0f;
        float s = e0 + e1;
        #pragma unroll
        for (int o = 16; o > 0; o >>= 1) s += __shfl_xor_sync(0xffffffffu, s, o);
        float inv = 1.0f / s;
        sl[lane] = e0 * inv;
        if (lane < 4) sl[32 + lane] = e1 * inv;
    }
    __syncthreads();

    // weighted sum of img_fc rows  (each thread: dims tid and tid+256)
    float acc0 = 0.0f, acc1 = 0.0f;
    const float* fc = g_img_fc + (size_t)b * R_REG * DOUT;
    #pragma unroll 4
    for (int r = 0; r < R_REG; r++) {
        float a = sl[r];
        acc0 += a * fc[(size_t)r * DOUT + tid];
        acc1 += a * fc[(size_t)r * DOUT + 256 + tid];
    }
    g_msg[(size_t)n * DOUT + tid]       = acc0 + bim[tid];
    g_msg[(size_t)n * DOUT + 256 + tid] = acc1 + bim[256 + tid];
}

// ---------------- CSR build ----------------
__global__ void zero_kernel() {
    int i = blockIdx.x * blockDim.x + threadIdx.x;
    if (i < N_NODES) { g_deg[i] = 0; g_cursor[i] = 0; }
}

__global__ void count_kernel(const int* __restrict__ dst) {
    int e = blockIdx.x * blockDim.x + threadIdx.x;
    if (e < E_EDGES) atomicAdd(&g_deg[dst[e]], 1);
}

__global__ void scan_kernel() {
    // single block, 1024 threads, chunk = 12 (12288 / 1024)
    __shared__ int s[1024];
    const int tid = threadIdx.x;
    const int chunk = N_NODES / 1024;
    const int base = tid * chunk;
    int sum = 0;
    #pragma unroll
    for (int i = 0; i < chunk; i++) sum += g_deg[base + i];
    s[tid] = sum;
    __syncthreads();
    for (int ofs = 1; ofs < 1024; ofs <<= 1) {
        int v = (tid >= ofs) ? s[tid - ofs] : 0;
        __syncthreads();
        if (tid >= ofs) s[tid] += v;
        __syncthreads();
    }
    int run = (tid == 0) ? 0 : s[tid - 1];
    #pragma unroll
    for (int i = 0; i < chunk; i++) {
        int idx = base + i;
        g_off[idx] = run;
        run += g_deg[idx];
    }
    if (tid == 0) g_off[N_NODES] = s[1023];
}

__global__ void fill_kernel(const int* __restrict__ src, const int* __restrict__ dst) {
    int e = blockIdx.x * blockDim.x + threadIdx.x;
    if (e < E_EDGES) {
        int d = dst[e];
        int pos = g_off[d] + atomicAdd(&g_cursor[d], 1);
        g_csr_src[pos] = src[e];
    }
}

// ---------------- Neighbor sum: msg[n] += sum_{e in in(n)} h1[src[e]] ----------------
__global__ __launch_bounds__(128) void neigh_kernel() {
    const int n = blockIdx.x;
    const int t = threadIdx.x;         // 128 threads, one float4 each (512 dims)
    const int s0 = g_off[n], s1 = g_off[n + 1];
    float4 acc = make_float4(0.f, 0.f, 0.f, 0.f);
    const float4* h1v = (const float4*)g_h1;
    int e = s0;
    #pragma unroll 1
    for (; e + 4 <= s1; e += 4) {
        int a0 = g_csr_src[e + 0], a1 = g_csr_src[e + 1];
        int a2 = g_csr_src[e + 2], a3 = g_csr_src[e + 3];
        float4 v0 = h1v[(size_t)a0 * 128 + t];
        float4 v1 = h1v[(size_t)a1 * 128 + t];
        float4 v2 = h1v[(size_t)a2 * 128 + t];
        float4 v3 = h1v[(size_t)a3 * 128 + t];
        acc.x += v0.x + v1.x + v2.x + v3.x;
        acc.y += v0.y + v1.y + v2.y + v3.y;
        acc.z += v0.z + v1.z + v2.z + v3.z;
        acc.w += v0.w + v1.w + v2.w + v3.w;
    }
    for (; e < s1; e++) {
        int a = g_csr_src[e];
        float4 v = h1v[(size_t)a * 128 + t];
        acc.x += v.x; acc.y += v.y; acc.z += v.z; acc.w += v.w;
    }
    float4* mv = (float4*)g_msg;
    float4 m = mv[(size_t)n * 128 + t];
    m.x += acc.x; m.y += acc.y; m.z += acc.z; m.w += acc.w;
    mv[(size_t)n * 128 + t] = m;
}

// ---------------- Host launcher ----------------
extern "C" void kernel_launch(void* const* d_in, const int* in_sizes, int n_in,
                              void* d_out, int out_size)
{
    const float* h         = (const float*)d_in[0];
    const float* img_feats = (const float*)d_in[1];
    const int*   batch_ids = (const int*)  d_in[2];
    const int*   src       = (const int*)  d_in[3];
    const int*   dst       = (const int*)  d_in[4];
    const float* Wf  = (const float*)d_in[5];
    const float* bf  = (const float*)d_in[6];
    const float* Wi  = (const float*)d_in[7];
    const float* bi  = (const float*)d_in[8];
    const float* Wa  = (const float*)d_in[9];
    const float* ba  = (const float*)d_in[10];
    const float* Wn  = (const float*)d_in[11];
    const float* bn  = (const float*)d_in[12];
    const float* Wim = (const float*)d_in[13];
    const float* bim = (const float*)d_in[14];
    const float* Wap = (const float*)d_in[15];
    const float* bap = (const float*)d_in[16];
    float* out = (float*)d_out;

    void *p_img_proj, *p_img_fc, *p_node_proj, *p_h1;
    cudaGetSymbolAddress(&p_img_proj,  g_img_proj);
    cudaGetSymbolAddress(&p_img_fc,    g_img_fc);
    cudaGetSymbolAddress(&p_node_proj, g_node_proj);
    cudaGetSymbolAddress(&p_h1,        g_h1);

    // CSR build
    zero_kernel<<<(N_NODES + 255) / 256, 256>>>();
    count_kernel<<<(E_EDGES + 255) / 256, 256>>>(dst);
    scan_kernel<<<1, 1024>>>();
    fill_kernel<<<(E_EDGES + 255) / 256, 256>>>(src, dst);

    // Dense projections
    // img_proj = img_feats @ Wi + bi      [2304 x 256], K=1024
    sgemm_kernel<<<dim3(PDIM / 128, BR / 128), 256>>>(
        img_feats, Wi, bi, (float*)p_img_proj, BR, PDIM, DIMG, 0);
    // img_fc = img_feats @ Wim            [2304 x 512], K=1024  (bim added in att kernel)
    sgemm_kernel<<<dim3(DOUT / 128, BR / 128), 256>>>(
        img_feats, Wim, nullptr, (float*)p_img_fc, BR, DOUT, DIMG, 0);
    // node_proj = h @ Wf + bf             [12288 x 256], K=512
    sgemm_kernel<<<dim3(PDIM / 128, N_NODES / 128), 256>>>(
        h, Wf, bf, (float*)p_node_proj, N_NODES, PDIM, DIN, 0);
    // h1 = h @ Wn + bn                    [12288 x 512], K=512
    sgemm_kernel<<<dim3(DOUT / 128, N_NODES / 128), 256>>>(
        h, Wn, bn, (float*)p_h1, N_NODES, DOUT, DIN, 0);

    // Attention + image message -> g_msg = bim + att @ img_fc
    att_kernel<<<N_NODES, 256>>>(batch_ids, Wa, ba, bim);

    // g_msg += segment_sum(h1[src], dst)
    neigh_kernel<<<N_NODES, 128>>>();

    // out = relu([msg | h1] @ Wap + bap)
    sgemm_cat_kernel<<<dim3(DOUT / 128, N_NODES / 128), 256>>>(Wap, bap, out);
}

// round 3
// speedup vs baseline: 1.5848x; 1.5848x over previous
#include <cuda_runtime.h>
#include <math.h>
#include <stdint.h>

// ---------------- Problem constants ----------------
#define N_NODES 12288
#define B_BATCH 64
#define R_REG   36
#define E_EDGES 196608
#define DIN     512
#define DOUT    512
#define PDIM    256
#define DIMG    1024
#define BR      (B_BATCH * R_REG)   // 2304

// ---------------- Scratch (device globals; no allocation allowed) ----------------
__device__ __align__(16) float g_img_proj[BR * PDIM];       // img_feats @ Wi + bi
__device__ __align__(16) float g_img_fc[BR * DOUT];         // img_feats @ Wim
__device__ __align__(16) float g_node_proj[N_NODES * PDIM]; // h @ Wf + bf
__device__ __align__(16) float g_h1[N_NODES * DOUT];        // h @ Wn + bn
__device__ __align__(16) float g_msg[N_NODES * DOUT];       // bim + att*img_fc + neigh
__device__ int g_deg[N_NODES];
__device__ int g_cursor[N_NODES];
__device__ int g_off[N_NODES + 1];
__device__ int g_csr_src[E_EDGES];

// ================= TF32 3x tensor-core GEMM =================
// C[M,N] = A[M,K] @ B[K,N] (+bias) (+relu), row-major everywhere.
// Block tile 128x128, K-chunk 16, double-buffered smem, 8 warps,
// warp tile 32(M) x 64(N), mma.sync.m16n8k8 tf32 with hi/lo split
// (3 MMAs per logical MMA) for ~fp32 accuracy.
// Optional concat input: if A2 != null, rows are [A | A2] along K
// (both with row pitch Apitch, split at K/2; K/2 must be a multiple of 16).

#define BMT 128
#define BNT 128
#define BKT 16
#define APITCH_S 20    // smem A row pitch (floats): conflict-free frag loads, 16B-aligned
#define BPITCH_S 136   // smem B row pitch (floats)

__device__ __forceinline__ uint32_t f2tf(float f) {
    uint32_t u;
    asm("cvt.rna.tf32.f32 %0, %1;" : "=r"(u) : "f"(f));
    return u;
}
__device__ __forceinline__ void split_tf32(float f, uint32_t& hi, uint32_t& lo) {
    hi = f2tf(f);
    lo = f2tf(f - __uint_as_float(hi));
}
__device__ __forceinline__ void mma_tf32(float* c, const uint32_t* a, uint32_t b0, uint32_t b1) {
    asm volatile(
        "mma.sync.aligned.m16n8k8.row.col.f32.tf32.tf32.f32 "
        "{%0,%1,%2,%3}, {%4,%5,%6,%7}, {%8,%9}, {%0,%1,%2,%3};\n"
        : "+f"(c[0]), "+f"(c[1]), "+f"(c[2]), "+f"(c[3])
        : "r"(a[0]), "r"(a[1]), "r"(a[2]), "r"(a[3]), "r"(b0), "r"(b1));
}

__global__ __launch_bounds__(256, 1) void gemm_tf32_kernel(
    const float* __restrict__ A, const float* __restrict__ A2, int Apitch,
    const float* __restrict__ B, const float* __restrict__ bias,
    float* __restrict__ C, int M, int N, int K, int do_relu)
{
    __shared__ float As[2][BMT * APITCH_S];
    __shared__ float Bs[2][BKT * BPITCH_S];

    const int tid  = threadIdx.x;
    const int bm0  = blockIdx.y * BMT;
    const int bn0  = blockIdx.x * BNT;
    const int lane = tid & 31;
    const int warp = tid >> 5;
    const int wm   = warp & 3;   // 0..3 -> rows [wm*32, +32)
    const int wn   = warp >> 2;  // 0..1 -> cols [wn*64, +64)
    const int gid  = lane >> 2;  // 0..7
    const int tig  = lane & 3;   // 0..3

    // global->smem load mapping
    const int lam = tid >> 1;          // A row within tile: 0..127
    const int lak = (tid & 1) * 8;     // A k offset: 0 or 8 (loads 8 floats)
    const int lbk = tid >> 4;          // B k row: 0..15
    const int lbn = (tid & 15) * 4;    // B col: 0,4,...,60 (plus +64 pass)

    float c[2][8][4];
    #pragma unroll
    for (int i = 0; i < 2; i++)
        #pragma unroll
        for (int j = 0; j < 8; j++)
            #pragma unroll
            for (int q = 0; q < 4; q++) c[i][j][q] = 0.0f;

    const int T = K / BKT;
    const int Khalf = K >> 1;

    float4 ar0, ar1, br0, br1;

    // ---- load chunk t into staging registers ----
    #define LOAD_G(t) do {                                                        \
        int k0 = (t) * BKT;                                                       \
        int kg = k0 + lak;                                                        \
        const float* Ab = A; int kk_ = kg;                                        \
        if (A2 != nullptr && kg >= Khalf) { Ab = A2; kk_ = kg - Khalf; }          \
        const float* pa = Ab + (size_t)(bm0 + lam) * Apitch + kk_;                \
        ar0 = *(const float4*)pa;                                                 \
        ar1 = *(const float4*)(pa + 4);                                           \
        const float* pb = B + (size_t)(k0 + lbk) * N + bn0 + lbn;                 \
        br0 = *(const float4*)pb;                                                 \
        br1 = *(const float4*)(pb + 64);                                          \
    } while (0)

    #define STORE_S(buf) do {                                                     \
        *(float4*)&As[buf][lam * APITCH_S + lak]     = ar0;                       \
        *(float4*)&As[buf][lam * APITCH_S + lak + 4] = ar1;                       \
        *(float4*)&Bs[buf][lbk * BPITCH_S + lbn]      = br0;                      \
        *(float4*)&Bs[buf][lbk * BPITCH_S + lbn + 64] = br1;                      \
    } while (0)

    LOAD_G(0);
    STORE_S(0);
    __syncthreads();

    for (int t = 0; t < T; t++) {
        const int buf = t & 1;
        if (t + 1 < T) LOAD_G(t + 1);

        const float* as = As[buf];
        const float* bs = Bs[buf];

        #pragma unroll
        for (int kk = 0; kk < BKT; kk += 8) {
            uint32_t ah[2][4], al[2][4];
            #pragma unroll
            for (int i = 0; i < 2; i++) {
                const int mr = wm * 32 + i * 16 + gid;
                float f0 = as[mr * APITCH_S + kk + tig];
                float f1 = as[(mr + 8) * APITCH_S + kk + tig];
                float f2 = as[mr * APITCH_S + kk + tig + 4];
                float f3 = as[(mr + 8) * APITCH_S + kk + tig + 4];
                split_tf32(f0, ah[i][0], al[i][0]);
                split_tf32(f1, ah[i][1], al[i][1]);
                split_tf32(f2, ah[i][2], al[i][2]);
                split_tf32(f3, ah[i][3], al[i][3]);
            }
            #pragma unroll
            for (int j = 0; j < 8; j++) {
                const int nc = wn * 64 + j * 8 + gid;
                float fb0 = bs[(kk + tig) * BPITCH_S + nc];
                float fb1 = bs[(kk + tig + 4) * BPITCH_S + nc];
                uint32_t bh0, bl0, bh1, bl1;
                split_tf32(fb0, bh0, bl0);
                split_tf32(fb1, bh1, bl1);
                #pragma unroll
                for (int i = 0; i < 2; i++) {
                    mma_tf32(c[i][j], ah[i], bh0, bh1);
                    mma_tf32(c[i][j], ah[i], bl0, bl1);
                    mma_tf32(c[i][j], al[i], bh0, bh1);
                }
            }
        }

        if (t + 1 < T) STORE_S(buf ^ 1);
        __syncthreads();
    }

    // ---- epilogue ----
    #pragma unroll
    for (int i = 0; i < 2; i++) {
        const int r0 = bm0 + wm * 32 + i * 16 + gid;
        #pragma unroll
        for (int j = 0; j < 8; j++) {
            const int col = bn0 + wn * 64 + j * 8 + tig * 2;
            float bv0 = bias ? bias[col]     : 0.0f;
            float bv1 = bias ? bias[col + 1] : 0.0f;
            float v0 = c[i][j][0] + bv0;
            float v1 = c[i][j][1] + bv1;
            float v2 = c[i][j][2] + bv0;
            float v3 = c[i][j][3] + bv1;
            if (do_relu) {
                v0 = fmaxf(v0, 0.0f); v1 = fmaxf(v1, 0.0f);
                v2 = fmaxf(v2, 0.0f); v3 = fmaxf(v3, 0.0f);
            }
            C[(size_t)r0 * N + col]           = v0;
            C[(size_t)r0 * N + col + 1]       = v1;
            C[(size_t)(r0 + 8) * N + col]     = v2;
            C[(size_t)(r0 + 8) * N + col + 1] = v3;
        }
    }
    #undef LOAD_G
    #undef STORE_S
}

// ---------------- Attention + image message (per node) ----------------
__device__ __forceinline__ float fast_tanh(float x) {
    float e = __expf(2.0f * x);
    return 1.0f - __fdividef(2.0f, e + 1.0f);
}

__global__ __launch_bounds__(256) void att_kernel(
    const int* __restrict__ batch_ids,
    const float* __restrict__ Wa, const float* __restrict__ ba,
    const float* __restrict__ bim)
{
    const int n = blockIdx.x;
    const int tid = threadIdx.x;        // 256
    const int lane = tid & 31, warp = tid >> 5;

    __shared__ float np[PDIM];
    __shared__ float wa[PDIM];
    __shared__ float sl[40];            // logits then att

    const int b = batch_ids[n];
    np[tid] = g_node_proj[(size_t)n * PDIM + tid];
    wa[tid] = Wa[tid];
    __syncthreads();

    // logits: warp w handles r = w, w+8, ...
    for (int r = warp; r < R_REG; r += 8) {
        const float* ip = g_img_proj + (size_t)(b * R_REG + r) * PDIM;
        float part = 0.0f;
        #pragma unroll
        for (int i = 0; i < 8; i++) {
            int p = lane + 32 * i;
            part += fast_tanh(np[p] + ip[p]) * wa[p];
        }
        #pragma unroll
        for (int o = 16; o > 0; o >>= 1) part += __shfl_xor_sync(0xffffffffu, part, o);
        if (lane == 0) sl[r] = part + ba[0];
    }
    __syncthreads();

    // softmax over 36 (warp 0)
    if (warp == 0) {
        float v0 = sl[lane];
        float v1 = (lane < 4) ? sl[32 + lane] : -INFINITY;
        float m = fmaxf(v0, v1);
        #pragma unroll
        for (int o = 16; o > 0; o >>= 1) m = fmaxf(m, __shfl_xor_sync(0xffffffffu, m, o));
        float e0 = __expf(v0 - m);
        float e1 = (lane < 4) ? __expf(v1 - m) : 0.0f;
        float s = e0 + e1;
        #pragma unroll
        for (int o = 16; o > 0; o >>= 1) s += __shfl_xor_sync(0xffffffffu, s, o);
        float inv = 1.0f / s;
        sl[lane] = e0 * inv;
        if (lane < 4) sl[32 + lane] = e1 * inv;
    }
    __syncthreads();

    // weighted sum of img_fc rows  (each thread: dims tid and tid+256)
    float acc0 = 0.0f, acc1 = 0.0f;
    const float* fc = g_img_fc + (size_t)b * R_REG * DOUT;
    #pragma unroll 4
    for (int r = 0; r < R_REG; r++) {
        float a = sl[r];
        acc0 += a * fc[(size_t)r * DOUT + tid];
        acc1 += a * fc[(size_t)r * DOUT + 256 + tid];
    }
    g_msg[(size_t)n * DOUT + tid]       = acc0 + bim[tid];
    g_msg[(size_t)n * DOUT + 256 + tid] = acc1 + bim[256 + tid];
}

// ---------------- CSR build ----------------
__global__ void zero_kernel() {
    int i = blockIdx.x * blockDim.x + threadIdx.x;
    if (i < N_NODES) { g_deg[i] = 0; g_cursor[i] = 0; }
}

__global__ void count_kernel(const int* __restrict__ dst) {
    int e = blockIdx.x * blockDim.x + threadIdx.x;
    if (e < E_EDGES) atomicAdd(&g_deg[dst[e]], 1);
}

__global__ void scan_kernel() {
    __shared__ int s[1024];
    const int tid = threadIdx.x;
    const int chunk = N_NODES / 1024;
    const int base = tid * chunk;
    int sum = 0;
    #pragma unroll
    for (int i = 0; i < chunk; i++) sum += g_deg[base + i];
    s[tid] = sum;
    __syncthreads();
    for (int ofs = 1; ofs < 1024; ofs <<= 1) {
        int v = (tid >= ofs) ? s[tid - ofs] : 0;
        __syncthreads();
        if (tid >= ofs) s[tid] += v;
        __syncthreads();
    }
    int run = (tid == 0) ? 0 : s[tid - 1];
    #pragma unroll
    for (int i = 0; i < chunk; i++) {
        int idx = base + i;
        g_off[idx] = run;
        run += g_deg[idx];
    }
    if (tid == 0) g_off[N_NODES] = s[1023];
}

__global__ void fill_kernel(const int* __restrict__ src, const int* __restrict__ dst) {
    int e = blockIdx.x * blockDim.x + threadIdx.x;
    if (e < E_EDGES) {
        int d = dst[e];
        int pos = g_off[d] + atomicAdd(&g_cursor[d], 1);
        g_csr_src[pos] = src[e];
    }
}

// ---------------- Neighbor sum: msg[n] += sum_{e in in(n)} h1[src[e]] ----------------
__global__ __launch_bounds__(128) void neigh_kernel() {
    const int n = blockIdx.x;
    const int t = threadIdx.x;         // 128 threads, one float4 each (512 dims)
    const int s0 = g_off[n], s1 = g_off[n + 1];
    float4 acc = make_float4(0.f, 0.f, 0.f, 0.f);
    const float4* h1v = (const float4*)g_h1;
    int e = s0;
    #pragma unroll 1
    for (; e + 4 <= s1; e += 4) {
        int a0 = g_csr_src[e + 0], a1 = g_csr_src[e + 1];
        int a2 = g_csr_src[e + 2], a3 = g_csr_src[e + 3];
        float4 v0 = h1v[(size_t)a0 * 128 + t];
        float4 v1 = h1v[(size_t)a1 * 128 + t];
        float4 v2 = h1v[(size_t)a2 * 128 + t];
        float4 v3 = h1v[(size_t)a3 * 128 + t];
        acc.x += v0.x + v1.x + v2.x + v3.x;
        acc.y += v0.y + v1.y + v2.y + v3.y;
        acc.z += v0.z + v1.z + v2.z + v3.z;
        acc.w += v0.w + v1.w + v2.w + v3.w;
    }
    for (; e < s1; e++) {
        int a = g_csr_src[e];
        float4 v = h1v[(size_t)a * 128 + t];
        acc.x += v.x; acc.y += v.y; acc.z += v.z; acc.w += v.w;
    }
    float4* mv = (float4*)g_msg;
    float4 m = mv[(size_t)n * 128 + t];
    m.x += acc.x; m.y += acc.y; m.z += acc.z; m.w += acc.w;
    mv[(size_t)n * 128 + t] = m;
}

// ---------------- Host launcher ----------------
extern "C" void kernel_launch(void* const* d_in, const int* in_sizes, int n_in,
                              void* d_out, int out_size)
{
    const float* h         = (const float*)d_in[0];
    const float* img_feats = (const float*)d_in[1];
    const int*   batch_ids = (const int*)  d_in[2];
    const int*   src       = (const int*)  d_in[3];
    const int*   dst       = (const int*)  d_in[4];
    const float* Wf  = (const float*)d_in[5];
    const float* bf  = (const float*)d_in[6];
    const float* Wi  = (const float*)d_in[7];
    const float* bi  = (const float*)d_in[8];
    const float* Wa  = (const float*)d_in[9];
    const float* ba  = (const float*)d_in[10];
    const float* Wn  = (const float*)d_in[11];
    const float* bn  = (const float*)d_in[12];
    const float* Wim = (const float*)d_in[13];
    const float* bim = (const float*)d_in[14];
    const float* Wap = (const float*)d_in[15];
    const float* bap = (const float*)d_in[16];
    float* out = (float*)d_out;

    void *p_img_proj, *p_img_fc, *p_node_proj, *p_h1, *p_msg;
    cudaGetSymbolAddress(&p_img_proj,  g_img_proj);
    cudaGetSymbolAddress(&p_img_fc,    g_img_fc);
    cudaGetSymbolAddress(&p_node_proj, g_node_proj);
    cudaGetSymbolAddress(&p_h1,        g_h1);
    cudaGetSymbolAddress(&p_msg,       g_msg);

    // CSR build
    zero_kernel<<<(N_NODES + 255) / 256, 256>>>();
    count_kernel<<<(E_EDGES + 255) / 256, 256>>>(dst);
    scan_kernel<<<1, 1024>>>();
    fill_kernel<<<(E_EDGES + 255) / 256, 256>>>(src, dst);

    // Dense projections (tf32 tensor cores, 3x split)
    // img_proj = img_feats @ Wi + bi      [2304 x 256], K=1024
    gemm_tf32_kernel<<<dim3(PDIM / BNT, BR / BMT), 256>>>(
        img_feats, nullptr, DIMG, Wi, bi, (float*)p_img_proj, BR, PDIM, DIMG, 0);
    // img_fc = img_feats @ Wim            [2304 x 512], K=1024  (bim added in att kernel)
    gemm_tf32_kernel<<<dim3(DOUT / BNT, BR / BMT), 256>>>(
        img_feats, nullptr, DIMG, Wim, nullptr, (float*)p_img_fc, BR, DOUT, DIMG, 0);
    // node_proj = h @ Wf + bf             [12288 x 256], K=512
    gemm_tf32_kernel<<<dim3(PDIM / BNT, N_NODES / BMT), 256>>>(
        h, nullptr, DIN, Wf, bf, (float*)p_node_proj, N_NODES, PDIM, DIN, 0);
    // h1 = h @ Wn + bn                    [12288 x 512], K=512
    gemm_tf32_kernel<<<dim3(DOUT / BNT, N_NODES / BMT), 256>>>(
        h, nullptr, DIN, Wn, bn, (float*)p_h1, N_NODES, DOUT, DIN, 0);

    // Attention + image message -> g_msg = bim + att @ img_fc
    att_kernel<<<N_NODES, 256>>>(batch_ids, Wa, ba, bim);

    // g_msg += segment_sum(h1[src], dst)
    neigh_kernel<<<N_NODES, 128>>>();

    // out = relu([msg | h1] @ Wap + bap), K=1024 concat split at 512
    gemm_tf32_kernel<<<dim3(DOUT / BNT, N_NODES / BMT), 256>>>(
        (const float*)p_msg, (const float*)p_h1, DOUT, Wap, bap, out,
        N_NODES, DOUT, 2 * DOUT, 1);
}

// round 4
// speedup vs baseline: 1.5886x; 1.0024x over previous
#include <cuda_runtime.h>
#include <math.h>
#include <stdint.h>

// ---------------- Problem constants ----------------
#define N_NODES 12288
#define B_BATCH 64
#define R_REG   36
#define E_EDGES 196608
#define DIN     512
#define DOUT    512
#define PDIM    256
#define DIMG    1024
#define BR      (B_BATCH * R_REG)   // 2304

// ---------------- Scratch (device globals; no allocation allowed) ----------------
__device__ __align__(16) float g_img_proj[BR * PDIM];       // img_feats @ Wi + bi
__device__ __align__(16) float g_img_fc[BR * DOUT];         // img_feats @ Wim
__device__ __align__(16) float g_node_proj[N_NODES * PDIM]; // h @ Wf + bf
__device__ __align__(16) float g_h1[N_NODES * DOUT];        // h @ Wn + bn
__device__ __align__(16) float g_msg[N_NODES * DOUT];       // bim + att*img_fc + neigh
__device__ int g_deg[N_NODES];
__device__ int g_cursor[N_NODES];
__device__ int g_off[N_NODES + 1];
__device__ int g_csr_src[E_EDGES];

// ================= TF32 3x tensor-core GEMM =================
// C[M,N] = A[M,K] @ B[K,N] (+bias) (+relu), row-major everywhere.
// Block tile 128x128, K-chunk 16, double-buffered smem, 8 warps,
// warp tile 32(M) x 64(N), mma.sync.m16n8k8 tf32 with hi/lo split
// (3 MMAs per logical MMA) for ~fp32 accuracy.
// Optional concat input: if A2 != null, rows are [A | A2] along K
// (both with row pitch Apitch, split at K/2; K/2 must be a multiple of 16).

#define BMT 128
#define BNT 128
#define BKT 16
#define APITCH_S 20    // smem A row pitch (floats): conflict-free frag loads, 16B-aligned
#define BPITCH_S 136   // smem B row pitch (floats)

__device__ __forceinline__ uint32_t f2tf(float f) {
    uint32_t u;
    asm("cvt.rna.tf32.f32 %0, %1;" : "=r"(u) : "f"(f));
    return u;
}
__device__ __forceinline__ void split_tf32(float f, uint32_t& hi, uint32_t& lo) {
    hi = f2tf(f);
    lo = f2tf(f - __uint_as_float(hi));
}
__device__ __forceinline__ void mma_tf32(float* c, const uint32_t* a, uint32_t b0, uint32_t b1) {
    asm volatile(
        "mma.sync.aligned.m16n8k8.row.col.f32.tf32.tf32.f32 "
        "{%0,%1,%2,%3}, {%4,%5,%6,%7}, {%8,%9}, {%0,%1,%2,%3};\n"
        : "+f"(c[0]), "+f"(c[1]), "+f"(c[2]), "+f"(c[3])
        : "r"(a[0]), "r"(a[1]), "r"(a[2]), "r"(a[3]), "r"(b0), "r"(b1));
}

__global__ __launch_bounds__(256, 1) void gemm_tf32_kernel(
    const float* __restrict__ A, const float* __restrict__ A2, int Apitch,
    const float* __restrict__ B, const float* __restrict__ bias,
    float* __restrict__ C, int M, int N, int K, int do_relu)
{
    __shared__ float As[2][BMT * APITCH_S];
    __shared__ float Bs[2][BKT * BPITCH_S];

    const int tid  = threadIdx.x;
    const int bm0  = blockIdx.y * BMT;
    const int bn0  = blockIdx.x * BNT;
    const int lane = tid & 31;
    const int warp = tid >> 5;
    const int wm   = warp & 3;   // 0..3 -> rows [wm*32, +32)
    const int wn   = warp >> 2;  // 0..1 -> cols [wn*64, +64)
    const int gid  = lane >> 2;  // 0..7
    const int tig  = lane & 3;   // 0..3

    // global->smem load mapping
    const int lam = tid >> 1;          // A row within tile: 0..127
    const int lak = (tid & 1) * 8;     // A k offset: 0 or 8 (loads 8 floats)
    const int lbk = tid >> 4;          // B k row: 0..15
    const int lbn = (tid & 15) * 4;    // B col: 0,4,...,60 (plus +64 pass)

    float c[2][8][4];
    #pragma unroll
    for (int i = 0; i < 2; i++)
        #pragma unroll
        for (int j = 0; j < 8; j++)
            #pragma unroll
            for (int q = 0; q < 4; q++) c[i][j][q] = 0.0f;

    const int T = K / BKT;
    const int Khalf = K >> 1;

    float4 ar0, ar1, br0, br1;

    // ---- load chunk t into staging registers ----
    #define LOAD_G(t) do {                                                        \
        int k0 = (t) * BKT;                                                       \
        int kg = k0 + lak;                                                        \
        const float* Ab = A; int kk_ = kg;                                        \
        if (A2 != nullptr && kg >= Khalf) { Ab = A2; kk_ = kg - Khalf; }          \
        const float* pa = Ab + (size_t)(bm0 + lam) * Apitch + kk_;                \
        ar0 = *(const float4*)pa;                                                 \
        ar1 = *(const float4*)(pa + 4);                                           \
        const float* pb = B + (size_t)(k0 + lbk) * N + bn0 + lbn;                 \
        br0 = *(const float4*)pb;                                                 \
        br1 = *(const float4*)(pb + 64);                                          \
    } while (0)

    #define STORE_S(buf) do {                                                     \
        *(float4*)&As[buf][lam * APITCH_S + lak]     = ar0;                       \
        *(float4*)&As[buf][lam * APITCH_S + lak + 4] = ar1;                       \
        *(float4*)&Bs[buf][lbk * BPITCH_S + lbn]      = br0;                      \
        *(float4*)&Bs[buf][lbk * BPITCH_S + lbn + 64] = br1;                      \
    } while (0)

    LOAD_G(0);
    STORE_S(0);
    __syncthreads();

    for (int t = 0; t < T; t++) {
        const int buf = t & 1;
        if (t + 1 < T) LOAD_G(t + 1);

        const float* as = As[buf];
        const float* bs = Bs[buf];

        #pragma unroll
        for (int kk = 0; kk < BKT; kk += 8) {
            uint32_t ah[2][4], al[2][4];
            #pragma unroll
            for (int i = 0; i < 2; i++) {
                const int mr = wm * 32 + i * 16 + gid;
                float f0 = as[mr * APITCH_S + kk + tig];
                float f1 = as[(mr + 8) * APITCH_S + kk + tig];
                float f2 = as[mr * APITCH_S + kk + tig + 4];
                float f3 = as[(mr + 8) * APITCH_S + kk + tig + 4];
                split_tf32(f0, ah[i][0], al[i][0]);
                split_tf32(f1, ah[i][1], al[i][1]);
                split_tf32(f2, ah[i][2], al[i][2]);
                split_tf32(f3, ah[i][3], al[i][3]);
            }
            #pragma unroll
            for (int j = 0; j < 8; j++) {
                const int nc = wn * 64 + j * 8 + gid;
                float fb0 = bs[(kk + tig) * BPITCH_S + nc];
                float fb1 = bs[(kk + tig + 4) * BPITCH_S + nc];
                uint32_t bh0, bl0, bh1, bl1;
                split_tf32(fb0, bh0, bl0);
                split_tf32(fb1, bh1, bl1);
                #pragma unroll
                for (int i = 0; i < 2; i++) {
                    mma_tf32(c[i][j], ah[i], bh0, bh1);
                    mma_tf32(c[i][j], ah[i], bl0, bl1);
                    mma_tf32(c[i][j], al[i], bh0, bh1);
                }
            }
        }

        if (t + 1 < T) STORE_S(buf ^ 1);
        __syncthreads();
    }

    // ---- epilogue ----
    #pragma unroll
    for (int i = 0; i < 2; i++) {
        const int r0 = bm0 + wm * 32 + i * 16 + gid;
        #pragma unroll
        for (int j = 0; j < 8; j++) {
            const int col = bn0 + wn * 64 + j * 8 + tig * 2;
            float bv0 = bias ? bias[col]     : 0.0f;
            float bv1 = bias ? bias[col + 1] : 0.0f;
            float v0 = c[i][j][0] + bv0;
            float v1 = c[i][j][1] + bv1;
            float v2 = c[i][j][2] + bv0;
            float v3 = c[i][j][3] + bv1;
            if (do_relu) {
                v0 = fmaxf(v0, 0.0f); v1 = fmaxf(v1, 0.0f);
                v2 = fmaxf(v2, 0.0f); v3 = fmaxf(v3, 0.0f);
            }
            C[(size_t)r0 * N + col]           = v0;
            C[(size_t)r0 * N + col + 1]       = v1;
            C[(size_t)(r0 + 8) * N + col]     = v2;
            C[(size_t)(r0 + 8) * N + col + 1] = v3;
        }
    }
    #undef LOAD_G
    #undef STORE_S
}

// ---------------- Attention + image message (per node) ----------------
__device__ __forceinline__ float fast_tanh(float x) {
    float e = __expf(2.0f * x);
    return 1.0f - __fdividef(2.0f, e + 1.0f);
}

__global__ __launch_bounds__(256) void att_kernel(
    const int* __restrict__ batch_ids,
    const float* __restrict__ Wa, const float* __restrict__ ba,
    const float* __restrict__ bim)
{
    const int n = blockIdx.x;
    const int tid = threadIdx.x;        // 256
    const int lane = tid & 31, warp = tid >> 5;

    __shared__ float np[PDIM];
    __shared__ float wa[PDIM];
    __shared__ float sl[40];            // logits then att

    const int b = batch_ids[n];
    np[tid] = g_node_proj[(size_t)n * PDIM + tid];
    wa[tid] = Wa[tid];
    __syncthreads();

    // logits: warp w handles r = w, w+8, ...
    for (int r = warp; r < R_REG; r += 8) {
        const float* ip = g_img_proj + (size_t)(b * R_REG + r) * PDIM;
        float part = 0.0f;
        #pragma unroll
        for (int i = 0; i < 8; i++) {
            int p = lane + 32 * i;
            part += fast_tanh(np[p] + ip[p]) * wa[p];
        }
        #pragma unroll
        for (int o = 16; o > 0; o >>= 1) part += __shfl_xor_sync(0xffffffffu, part, o);
        if (lane == 0) sl[r] = part + ba[0];
    }
    __syncthreads();

    // softmax over 36 (warp 0)
    if (warp == 0) {
        float v0 = sl[lane];
        float v1 = (lane < 4) ? sl[32 + lane] : -INFINITY;
        float m = fmaxf(v0, v1);
        #pragma unroll
        for (int o = 16; o > 0; o >>= 1) m = fmaxf(m, __shfl_xor_sync(0xffffffffu, m, o));
        float e0 = __expf(v0 - m);
        float e1 = (lane < 4) ? __expf(v1 - m) : 0.0f;
        float s = e0 + e1;
        #pragma unroll
        for (int o = 16; o > 0; o >>= 1) s += __shfl_xor_sync(0xffffffffu, s, o);
        float inv = 1.0f / s;
        sl[lane] = e0 * inv;
        if (lane < 4) sl[32 + lane] = e1 * inv;
    }
    __syncthreads();

    // weighted sum of img_fc rows  (each thread: dims tid and tid+256)
    float acc0 = 0.0f, acc1 = 0.0f;
    const float* fc = g_img_fc + (size_t)b * R_REG * DOUT;
    #pragma unroll 4
    for (int r = 0; r < R_REG; r++) {
        float a = sl[r];
        acc0 += a * fc[(size_t)r * DOUT + tid];
        acc1 += a * fc[(size_t)r * DOUT + 256 + tid];
    }
    g_msg[(size_t)n * DOUT + tid]       = acc0 + bim[tid];
    g_msg[(size_t)n * DOUT + 256 + tid] = acc1 + bim[256 + tid];
}

// ---------------- CSR build ----------------
__global__ void zero_kernel() {
    int i = blockIdx.x * blockDim.x + threadIdx.x;
    if (i < N_NODES) { g_deg[i] = 0; g_cursor[i] = 0; }
}

__global__ void count_kernel(const int* __restrict__ dst) {
    int e = blockIdx.x * blockDim.x + threadIdx.x;
    if (e < E_EDGES) atomicAdd(&g_deg[dst[e]], 1);
}

__global__ void scan_kernel() {
    __shared__ int s[1024];
    const int tid = threadIdx.x;
    const int chunk = N_NODES / 1024;
    const int base = tid * chunk;
    int sum = 0;
    #pragma unroll
    for (int i = 0; i < chunk; i++) sum += g_deg[base + i];
    s[tid] = sum;
    __syncthreads();
    for (int ofs = 1; ofs < 1024; ofs <<= 1) {
        int v = (tid >= ofs) ? s[tid - ofs] : 0;
        __syncthreads();
        if (tid >= ofs) s[tid] += v;
        __syncthreads();
    }
    int run = (tid == 0) ? 0 : s[tid - 1];
    #pragma unroll
    for (int i = 0; i < chunk; i++) {
        int idx = base + i;
        g_off[idx] = run;
        run += g_deg[idx];
    }
    if (tid == 0) g_off[N_NODES] = s[1023];
}

__global__ void fill_kernel(const int* __restrict__ src, const int* __restrict__ dst) {
    int e = blockIdx.x * blockDim.x + threadIdx.x;
    if (e < E_EDGES) {
        int d = dst[e];
        int pos = g_off[d] + atomicAdd(&g_cursor[d], 1);
        g_csr_src[pos] = src[e];
    }
}

// ---------------- Neighbor sum: msg[n] += sum_{e in in(n)} h1[src[e]] ----------------
__global__ __launch_bounds__(128) void neigh_kernel() {
    const int n = blockIdx.x;
    const int t = threadIdx.x;         // 128 threads, one float4 each (512 dims)
    const int s0 = g_off[n], s1 = g_off[n + 1];
    float4 acc = make_float4(0.f, 0.f, 0.f, 0.f);
    const float4* h1v = (const float4*)g_h1;
    int e = s0;
    #pragma unroll 1
    for (; e + 4 <= s1; e += 4) {
        int a0 = g_csr_src[e + 0], a1 = g_csr_src[e + 1];
        int a2 = g_csr_src[e + 2], a3 = g_csr_src[e + 3];
        float4 v0 = h1v[(size_t)a0 * 128 + t];
        float4 v1 = h1v[(size_t)a1 * 128 + t];
        float4 v2 = h1v[(size_t)a2 * 128 + t];
        float4 v3 = h1v[(size_t)a3 * 128 + t];
        acc.x += v0.x + v1.x + v2.x + v3.x;
        acc.y += v0.y + v1.y + v2.y + v3.y;
        acc.z += v0.z + v1.z + v2.z + v3.z;
        acc.w += v0.w + v1.w + v2.w + v3.w;
    }
    for (; e < s1; e++) {
        int a = g_csr_src[e];
        float4 v = h1v[(size_t)a * 128 + t];
        acc.x += v.x; acc.y += v.y; acc.z += v.z; acc.w += v.w;
    }
    float4* mv = (float4*)g_msg;
    float4 m = mv[(size_t)n * 128 + t];
    m.x += acc.x; m.y += acc.y; m.z += acc.z; m.w += acc.w;
    mv[(size_t)n * 128 + t] = m;
}

// ---------------- Host launcher ----------------
extern "C" void kernel_launch(void* const* d_in, const int* in_sizes, int n_in,
                              void* d_out, int out_size)
{
    const float* h         = (const float*)d_in[0];
    const float* img_feats = (const float*)d_in[1];
    const int*   batch_ids = (const int*)  d_in[2];
    const int*   src       = (const int*)  d_in[3];
    const int*   dst       = (const int*)  d_in[4];
    const float* Wf  = (const float*)d_in[5];
    const float* bf  = (const float*)d_in[6];
    const float* Wi  = (const float*)d_in[7];
    const float* bi  = (const float*)d_in[8];
    const float* Wa  = (const float*)d_in[9];
    const float* ba  = (const float*)d_in[10];
    const float* Wn  = (const float*)d_in[11];
    const float* bn  = (const float*)d_in[12];
    const float* Wim = (const float*)d_in[13];
    const float* bim = (const float*)d_in[14];
    const float* Wap = (const float*)d_in[15];
    const float* bap = (const float*)d_in[16];
    float* out = (float*)d_out;

    void *p_img_proj, *p_img_fc, *p_node_proj, *p_h1, *p_msg;
    cudaGetSymbolAddress(&p_img_proj,  g_img_proj);
    cudaGetSymbolAddress(&p_img_fc,    g_img_fc);
    cudaGetSymbolAddress(&p_node_proj, g_node_proj);
    cudaGetSymbolAddress(&p_h1,        g_h1);
    cudaGetSymbolAddress(&p_msg,       g_msg);

    // CSR build
    zero_kernel<<<(N_NODES + 255) / 256, 256>>>();
    count_kernel<<<(E_EDGES + 255) / 256, 256>>>(dst);
    scan_kernel<<<1, 1024>>>();
    fill_kernel<<<(E_EDGES + 255) / 256, 256>>>(src, dst);

    // Dense projections (tf32 tensor cores, 3x split)
    // img_proj = img_feats @ Wi + bi      [2304 x 256], K=1024
    gemm_tf32_kernel<<<dim3(PDIM / BNT, BR / BMT), 256>>>(
        img_feats, nullptr, DIMG, Wi, bi, (float*)p_img_proj, BR, PDIM, DIMG, 0);
    // img_fc = img_feats @ Wim            [2304 x 512], K=1024  (bim added in att kernel)
    gemm_tf32_kernel<<<dim3(DOUT / BNT, BR / BMT), 256>>>(
        img_feats, nullptr, DIMG, Wim, nullptr, (float*)p_img_fc, BR, DOUT, DIMG, 0);
    // node_proj = h @ Wf + bf             [12288 x 256], K=512
    gemm_tf32_kernel<<<dim3(PDIM / BNT, N_NODES / BMT), 256>>>(
        h, nullptr, DIN, Wf, bf, (float*)p_node_proj, N_NODES, PDIM, DIN, 0);
    // h1 = h @ Wn + bn                    [12288 x 512], K=512
    gemm_tf32_kernel<<<dim3(DOUT / BNT, N_NODES / BMT), 256>>>(
        h, nullptr, DIN, Wn, bn, (float*)p_h1, N_NODES, DOUT, DIN, 0);

    // Attention + image message -> g_msg = bim + att @ img_fc
    att_kernel<<<N_NODES, 256>>>(batch_ids, Wa, ba, bim);

    // g_msg += segment_sum(h1[src], dst)
    neigh_kernel<<<N_NODES, 128>>>();

    // out = relu([msg | h1] @ Wap + bap), K=1024 concat split at 512
    gemm_tf32_kernel<<<dim3(DOUT / BNT, N_NODES / BMT), 256>>>(
        (const float*)p_msg, (const float*)p_h1, DOUT, Wap, bap, out,
        N_NODES, DOUT, 2 * DOUT, 1);
}

// round 6
// speedup vs baseline: 2.1541x; 1.3560x over previous
#include <cuda_runtime.h>
#include <math.h>
#include <stdint.h>

// ---------------- Problem constants ----------------
#define N_NODES 12288
#define B_BATCH 64
#define R_REG   36
#define E_EDGES 196608
#define DIN     512
#define DOUT    512
#define PDIM    256
#define DIMG    1024
#define BR      (B_BATCH * R_REG)   // 2304

// ---------------- Scratch (device globals; no allocation allowed) ----------------
__device__ __align__(16) float g_img_proj[BR * PDIM];       // img_feats @ Wi + bi
__device__ __align__(16) float g_img_fc[BR * DOUT];         // img_feats @ Wim
__device__ __align__(16) float g_node_proj[N_NODES * PDIM]; // h @ Wf + bf
__device__ __align__(16) float g_h1[N_NODES * DOUT];        // h @ Wn + bn
__device__ __align__(16) float g_msg[N_NODES * DOUT];       // bim + att*img_fc + neigh
__device__ int g_deg[N_NODES];
__device__ int g_cursor[N_NODES];
__device__ int g_off[N_NODES + 1];
__device__ int g_csr_src[E_EDGES];
// batch CSR
__device__ int g_bdeg[B_BATCH];
__device__ int g_bcur[B_BATCH];
__device__ int g_boff[B_BATCH + 1];
__device__ int g_bnodes[N_NODES];

// ================= bf16 2-split tensor-core GEMM =================
// C = A[M,K] @ B[K,N] (+bias)(+relu). A split into bf16 hi+lo; computes
// hi*hi + hi*lo + lo*hi with mma.sync.m16n8k16 (error ~2^-17 per operand).
// Block tile 128x128, K-chunk 16, double-buffered, 8 warps (4m x 2n),
// warp tile 32x64. Dual output: column-blocks [0,N1) -> set1, rest -> set2.
// Optional row-concat input A|A2 along K (split at K/2, pitch Apitch each).

#define PIT 9   // smem row pitch in b32 words (8 data + 1 pad)

__device__ __forceinline__ uint32_t pack_bf2(float f0, float f1) {
    // f0 -> lower 16 bits, f1 -> upper
    uint32_t w;
    asm("cvt.rn.bf16x2.f32 %0, %1, %2;" : "=r"(w) : "f"(f1), "f"(f0));
    return w;
}
__device__ __forceinline__ void split2(float f0, float f1, uint32_t& whi, uint32_t& wlo) {
    whi = pack_bf2(f0, f1);
    float h0 = __uint_as_float(whi << 16);
    float h1 = __uint_as_float(whi & 0xffff0000u);
    wlo = pack_bf2(f0 - h0, f1 - h1);
}
__device__ __forceinline__ void mma_bf16(float* c, const uint32_t* a, uint32_t b0, uint32_t b1) {
    asm volatile(
        "mma.sync.aligned.m16n8k16.row.col.f32.bf16.bf16.f32 "
        "{%0,%1,%2,%3}, {%4,%5,%6,%7}, {%8,%9}, {%0,%1,%2,%3};\n"
        : "+f"(c[0]), "+f"(c[1]), "+f"(c[2]), "+f"(c[3])
        : "r"(a[0]), "r"(a[1]), "r"(a[2]), "r"(a[3]), "r"(b0), "r"(b1));
}

__global__ __launch_bounds__(256) void gemm_bf16_kernel(
    const float* __restrict__ A, const float* __restrict__ A2, int Apitch,
    const float* __restrict__ B1, const float* __restrict__ bias1, float* __restrict__ C1, int N1,
    const float* __restrict__ B2, const float* __restrict__ bias2, float* __restrict__ C2, int N2,
    int K, int do_relu)
{
    __shared__ uint32_t Ah[2][128 * PIT], Al[2][128 * PIT];
    __shared__ uint32_t Bh[2][128 * PIT], Bl[2][128 * PIT];

    const int tid = threadIdx.x;
    const int bm0 = blockIdx.y * 128;
    const int bx = blockIdx.x;

    const float* Bp; const float* bias; float* C; int N; int bn0;
    if (bx * 128 < N1) { Bp = B1; bias = bias1; C = C1; N = N1; bn0 = bx * 128; }
    else               { Bp = B2; bias = bias2; C = C2; N = N2; bn0 = bx * 128 - N1; }

    const int lane = tid & 31, warp = tid >> 5;
    const int wm = warp & 3, wn = warp >> 2;
    const int gid = lane >> 2, tig = lane & 3;

    const int lam = tid >> 1, lak = (tid & 1) * 8;     // A: row, k-offset
    const int lbn = tid & 127, lbk = (tid >> 7) * 8;   // B: col, k-offset

    float c[2][8][4];
    #pragma unroll
    for (int i = 0; i < 2; i++)
        #pragma unroll
        for (int j = 0; j < 8; j++)
            #pragma unroll
            for (int q = 0; q < 4; q++) c[i][j][q] = 0.0f;

    const int T = K / 16;
    const int Khalf = K >> 1;

    float a_st[8], b_st[8];

    #define LOAD_G(t) do {                                                       \
        int kg = (t) * 16 + lak;                                                 \
        const float* Ab = A; int kk_ = kg;                                       \
        if (A2 != nullptr && kg >= Khalf) { Ab = A2; kk_ = kg - Khalf; }         \
        const float* pa = Ab + (size_t)(bm0 + lam) * Apitch + kk_;               \
        float4 v0 = *(const float4*)pa;                                          \
        float4 v1 = *(const float4*)(pa + 4);                                    \
        a_st[0]=v0.x; a_st[1]=v0.y; a_st[2]=v0.z; a_st[3]=v0.w;                  \
        a_st[4]=v1.x; a_st[5]=v1.y; a_st[6]=v1.z; a_st[7]=v1.w;                  \
        int kb = (t) * 16 + lbk;                                                 \
        _Pragma("unroll")                                                        \
        for (int q = 0; q < 8; q++)                                              \
            b_st[q] = Bp[(size_t)(kb + q) * N + bn0 + lbn];                      \
    } while (0)

    #define STORE_S(buf) do {                                                    \
        int ba_ = lam * PIT + (lak >> 1);                                        \
        _Pragma("unroll")                                                        \
        for (int p = 0; p < 4; p++) {                                            \
            uint32_t hi_, lo_;                                                   \
            split2(a_st[2*p], a_st[2*p+1], hi_, lo_);                            \
            Ah[buf][ba_ + p] = hi_; Al[buf][ba_ + p] = lo_;                      \
        }                                                                        \
        int bb_ = lbn * PIT + (lbk >> 1);                                        \
        _Pragma("unroll")                                                        \
        for (int p = 0; p < 4; p++) {                                            \
            uint32_t hi_, lo_;                                                   \
            split2(b_st[2*p], b_st[2*p+1], hi_, lo_);                            \
            Bh[buf][bb_ + p] = hi_; Bl[buf][bb_ + p] = lo_;                      \
        }                                                                        \
    } while (0)

    LOAD_G(0);
    STORE_S(0);
    __syncthreads();

    for (int t = 0; t < T; t++) {
        const int buf = t & 1;
        if (t + 1 < T) LOAD_G(t + 1);

        const uint32_t* ah = Ah[buf];
        const uint32_t* al = Al[buf];
        const uint32_t* bh = Bh[buf];
        const uint32_t* bl = Bl[buf];

        uint32_t fah[2][4], fal[2][4];
        #pragma unroll
        for (int i = 0; i < 2; i++) {
            const int r = wm * 32 + i * 16 + gid;
            fah[i][0] = ah[r * PIT + tig];
            fah[i][1] = ah[(r + 8) * PIT + tig];
            fah[i][2] = ah[r * PIT + tig + 4];
            fah[i][3] = ah[(r + 8) * PIT + tig + 4];
            fal[i][0] = al[r * PIT + tig];
            fal[i][1] = al[(r + 8) * PIT + tig];
            fal[i][2] = al[r * PIT + tig + 4];
            fal[i][3] = al[(r + 8) * PIT + tig + 4];
        }
        #pragma unroll
        for (int j = 0; j < 8; j++) {
            const int n = wn * 64 + j * 8 + gid;
            uint32_t bh0 = bh[n * PIT + tig], bh1 = bh[n * PIT + tig + 4];
            uint32_t bl0 = bl[n * PIT + tig], bl1 = bl[n * PIT + tig + 4];
            #pragma unroll
            for (int i = 0; i < 2; i++) {
                mma_bf16(c[i][j], fah[i], bh0, bh1);
                mma_bf16(c[i][j], fah[i], bl0, bl1);
                mma_bf16(c[i][j], fal[i], bh0, bh1);
            }
        }

        if (t + 1 < T) STORE_S(buf ^ 1);
        __syncthreads();
    }

    #pragma unroll
    for (int i = 0; i < 2; i++) {
        const int r0 = bm0 + wm * 32 + i * 16 + gid;
        #pragma unroll
        for (int j = 0; j < 8; j++) {
            const int col = bn0 + wn * 64 + j * 8 + tig * 2;
            float bv0 = bias ? bias[col]     : 0.0f;
            float bv1 = bias ? bias[col + 1] : 0.0f;
            float v0 = c[i][j][0] + bv0;
            float v1 = c[i][j][1] + bv1;
            float v2 = c[i][j][2] + bv0;
            float v3 = c[i][j][3] + bv1;
            if (do_relu) {
                v0 = fmaxf(v0, 0.0f); v1 = fmaxf(v1, 0.0f);
                v2 = fmaxf(v2, 0.0f); v3 = fmaxf(v3, 0.0f);
            }
            C[(size_t)r0 * N + col]           = v0;
            C[(size_t)r0 * N + col + 1]       = v1;
            C[(size_t)(r0 + 8) * N + col]     = v2;
            C[(size_t)(r0 + 8) * N + col + 1] = v3;
        }
    }
    #undef LOAD_G
    #undef STORE_S
}

// ---------------- Batch-grouped attention ----------------
// One block per (batch, half). Batch's img_proj (36x256) and img_fc (36x512)
// staged in dynamic smem; warps process nodes of the batch independently.
#define ATT_SPLIT 2
#define ATT_SMEM_FLOATS (R_REG * PDIM + R_REG * DOUT + 8 * 40)
#define ATT_SMEM_BYTES  (ATT_SMEM_FLOATS * 4)

__device__ __forceinline__ float htanh(float x) {
    float y;
    asm("tanh.approx.f32 %0, %1;" : "=f"(y) : "f"(x));
    return y;
}

__global__ __launch_bounds__(256) void att2_kernel(
    const float* __restrict__ Wa, const float* __restrict__ ba,
    const float* __restrict__ bim)
{
    extern __shared__ float s_dyn[];
    float* s_ip  = s_dyn;                          // 36*256
    float* s_fc  = s_dyn + R_REG * PDIM;           // 36*512
    float* s_att = s_dyn + R_REG * PDIM + R_REG * DOUT;  // 8*40

    const int b = blockIdx.y;
    const int s = blockIdx.x;
    const int tid = threadIdx.x;
    const int lane = tid & 31, warp = tid >> 5;

    // stage batch image data
    {
        const float4* src1 = (const float4*)(g_img_proj + (size_t)b * R_REG * PDIM);
        float4* dst1 = (float4*)s_ip;
        for (int i = tid; i < R_REG * PDIM / 4; i += 256) dst1[i] = src1[i];
        const float4* src2 = (const float4*)(g_img_fc + (size_t)b * R_REG * DOUT);
        float4* dst2 = (float4*)s_fc;
        for (int i = tid; i < R_REG * DOUT / 4; i += 256) dst2[i] = src2[i];
    }
    __syncthreads();

    float wa[8];
    #pragma unroll
    for (int i = 0; i < 8; i++) wa[i] = Wa[lane + 32 * i];
    const float ba0 = ba[0];

    const int start = g_boff[b], end = g_boff[b + 1];
    float* sa = s_att + warp * 40;

    for (int idx = start + s * 8 + warp; idx < end; idx += ATT_SPLIT * 8) {
        const int n = g_bnodes[idx];

        float np[8];
        #pragma unroll
        for (int i = 0; i < 8; i++) np[i] = g_node_proj[(size_t)n * PDIM + lane + 32 * i];

        // logits
        for (int r = 0; r < R_REG; r++) {
            const float* ip = s_ip + r * PDIM;
            float part = 0.0f;
            #pragma unroll
            for (int i = 0; i < 8; i++)
                part += htanh(np[i] + ip[lane + 32 * i]) * wa[i];
            #pragma unroll
            for (int o = 16; o > 0; o >>= 1) part += __shfl_xor_sync(0xffffffffu, part, o);
            if (lane == 0) sa[r] = part + ba0;
        }
        __syncwarp();

        // softmax over 36
        {
            float v0 = sa[lane];
            float v1 = (lane < 4) ? sa[32 + lane] : -INFINITY;
            float m = fmaxf(v0, v1);
            #pragma unroll
            for (int o = 16; o > 0; o >>= 1) m = fmaxf(m, __shfl_xor_sync(0xffffffffu, m, o));
            float e0 = __expf(v0 - m);
            float e1 = (lane < 4) ? __expf(v1 - m) : 0.0f;
            float ssum = e0 + e1;
            #pragma unroll
            for (int o = 16; o > 0; o >>= 1) ssum += __shfl_xor_sync(0xffffffffu, ssum, o);
            float inv = 1.0f / ssum;
            sa[lane] = e0 * inv;
            if (lane < 4) sa[32 + lane] = e1 * inv;
        }
        __syncwarp();

        // weighted sum over regions
        float4 acc[4];
        #pragma unroll
        for (int q = 0; q < 4; q++) acc[q] = make_float4(0.f, 0.f, 0.f, 0.f);
        for (int r = 0; r < R_REG; r++) {
            float a = sa[r];
            #pragma unroll
            for (int q = 0; q < 4; q++) {
                float4 v = *(const float4*)&s_fc[r * DOUT + q * 128 + lane * 4];
                acc[q].x += a * v.x; acc[q].y += a * v.y;
                acc[q].z += a * v.z; acc[q].w += a * v.w;
            }
        }
        #pragma unroll
        for (int q = 0; q < 4; q++) {
            float4 bv = *(const float4*)&bim[q * 128 + lane * 4];
            acc[q].x += bv.x; acc[q].y += bv.y; acc[q].z += bv.z; acc[q].w += bv.w;
            *(float4*)&g_msg[(size_t)n * DOUT + q * 128 + lane * 4] = acc[q];
        }
        __syncwarp();
    }
}

// ---------------- CSR build (edge CSR + batch CSR folded in) ----------------
__global__ void zero_kernel() {
    int i = blockIdx.x * blockDim.x + threadIdx.x;
    if (i < N_NODES) { g_deg[i] = 0; g_cursor[i] = 0; }
    if (i < B_BATCH) { g_bdeg[i] = 0; g_bcur[i] = 0; }
}

__global__ void count_kernel(const int* __restrict__ dst, const int* __restrict__ batch_ids) {
    int e = blockIdx.x * blockDim.x + threadIdx.x;
    if (e < E_EDGES) atomicAdd(&g_deg[dst[e]], 1);
    if (e < N_NODES) atomicAdd(&g_bdeg[batch_ids[e]], 1);
}

__global__ void scan_kernel() {
    __shared__ int s[1024];
    const int tid = threadIdx.x;
    if (tid == 0) {  // batch prefix (64 entries, serial)
        int run = 0;
        for (int b = 0; b < B_BATCH; b++) { g_boff[b] = run; run += g_bdeg[b]; }
        g_boff[B_BATCH] = run;
    }
    const int chunk = N_NODES / 1024;
    const int base = tid * chunk;
    int sum = 0;
    #pragma unroll
    for (int i = 0; i < chunk; i++) sum += g_deg[base + i];
    s[tid] = sum;
    __syncthreads();
    for (int ofs = 1; ofs < 1024; ofs <<= 1) {
        int v = (tid >= ofs) ? s[tid - ofs] : 0;
        __syncthreads();
        if (tid >= ofs) s[tid] += v;
        __syncthreads();
    }
    int run = (tid == 0) ? 0 : s[tid - 1];
    #pragma unroll
    for (int i = 0; i < chunk; i++) {
        int idx = base + i;
        g_off[idx] = run;
        run += g_deg[idx];
    }
    if (tid == 0) g_off[N_NODES] = s[1023];
}

__global__ void fill_kernel(const int* __restrict__ src, const int* __restrict__ dst,
                            const int* __restrict__ batch_ids) {
    int e = blockIdx.x * blockDim.x + threadIdx.x;
    if (e < E_EDGES) {
        int d = dst[e];
        int pos = g_off[d] + atomicAdd(&g_cursor[d], 1);
        g_csr_src[pos] = src[e];
    }
    if (e < N_NODES) {
        int b = batch_ids[e];
        int pos = g_boff[b] + atomicAdd(&g_bcur[b], 1);
        g_bnodes[pos] = e;
    }
}

// ---------------- Neighbor sum: msg[n] += sum_{e in in(n)} h1[src[e]] ----------------
__global__ __launch_bounds__(128) void neigh_kernel() {
    const int n = blockIdx.x;
    const int t = threadIdx.x;
    const int s0 = g_off[n], s1 = g_off[n + 1];
    float4 acc = make_float4(0.f, 0.f, 0.f, 0.f);
    const float4* h1v = (const float4*)g_h1;
    int e = s0;
    #pragma unroll 1
    for (; e + 4 <= s1; e += 4) {
        int a0 = g_csr_src[e + 0], a1 = g_csr_src[e + 1];
        int a2 = g_csr_src[e + 2], a3 = g_csr_src[e + 3];
        float4 v0 = h1v[(size_t)a0 * 128 + t];
        float4 v1 = h1v[(size_t)a1 * 128 + t];
        float4 v2 = h1v[(size_t)a2 * 128 + t];
        float4 v3 = h1v[(size_t)a3 * 128 + t];
        acc.x += v0.x + v1.x + v2.x + v3.x;
        acc.y += v0.y + v1.y + v2.y + v3.y;
        acc.z += v0.z + v1.z + v2.z + v3.z;
        acc.w += v0.w + v1.w + v2.w + v3.w;
    }
    for (; e < s1; e++) {
        int a = g_csr_src[e];
        float4 v = h1v[(size_t)a * 128 + t];
        acc.x += v.x; acc.y += v.y; acc.z += v.z; acc.w += v.w;
    }
    float4* mv = (float4*)g_msg;
    float4 m = mv[(size_t)n * 128 + t];
    m.x += acc.x; m.y += acc.y; m.z += acc.z; m.w += acc.w;
    mv[(size_t)n * 128 + t] = m;
}

// ---------------- Host launcher ----------------
extern "C" void kernel_launch(void* const* d_in, const int* in_sizes, int n_in,
                              void* d_out, int out_size)
{
    const float* h         = (const float*)d_in[0];
    const float* img_feats = (const float*)d_in[1];
    const int*   batch_ids = (const int*)  d_in[2];
    const int*   src       = (const int*)  d_in[3];
    const int*   dst       = (const int*)  d_in[4];
    const float* Wf  = (const float*)d_in[5];
    const float* bf  = (const float*)d_in[6];
    const float* Wi  = (const float*)d_in[7];
    const float* bi  = (const float*)d_in[8];
    const float* Wa  = (const float*)d_in[9];
    const float* ba  = (const float*)d_in[10];
    const float* Wn  = (const float*)d_in[11];
    const float* bn  = (const float*)d_in[12];
    const float* Wim = (const float*)d_in[13];
    const float* bim = (const float*)d_in[14];
    const float* Wap = (const float*)d_in[15];
    const float* bap = (const float*)d_in[16];
    float* out = (float*)d_out;

    void *p_img_proj, *p_img_fc, *p_node_proj, *p_h1, *p_msg;
    cudaGetSymbolAddress(&p_img_proj,  g_img_proj);
    cudaGetSymbolAddress(&p_img_fc,    g_img_fc);
    cudaGetSymbolAddress(&p_node_proj, g_node_proj);
    cudaGetSymbolAddress(&p_h1,        g_h1);
    cudaGetSymbolAddress(&p_msg,       g_msg);

    cudaFuncSetAttribute(att2_kernel,
                         cudaFuncAttributeMaxDynamicSharedMemorySize, ATT_SMEM_BYTES);

    // CSR build (edge CSR + batch CSR)
    zero_kernel<<<(N_NODES + 255) / 256, 256>>>();
    count_kernel<<<(E_EDGES + 255) / 256, 256>>>(dst, batch_ids);
    scan_kernel<<<1, 1024>>>();
    fill_kernel<<<(E_EDGES + 255) / 256, 256>>>(src, dst, batch_ids);

    // img_proj = img_feats@Wi+bi [2304x256]; img_fc = img_feats@Wim [2304x512]
    gemm_bf16_kernel<<<dim3((PDIM + DOUT) / 128, BR / 128), 256>>>(
        img_feats, nullptr, DIMG,
        Wi, bi, (float*)p_img_proj, PDIM,
        Wim, nullptr, (float*)p_img_fc, DOUT,
        DIMG, 0);

    // node_proj = h@Wf+bf [12288x256]; h1 = h@Wn+bn [12288x512]
    gemm_bf16_kernel<<<dim3((PDIM + DOUT) / 128, N_NODES / 128), 256>>>(
        h, nullptr, DIN,
        Wf, bf, (float*)p_node_proj, PDIM,
        Wn, bn, (float*)p_h1, DOUT,
        DIN, 0);

    // g_msg = bim + att @ img_fc  (batch-grouped, smem-staged)
    att2_kernel<<<dim3(ATT_SPLIT, B_BATCH), 256, ATT_SMEM_BYTES>>>(Wa, ba, bim);

    // g_msg += segment_sum(h1[src], dst)
    neigh_kernel<<<N_NODES, 128>>>();

    // out = relu([msg | h1] @ Wap + bap)
    gemm_bf16_kernel<<<dim3(DOUT / 128, N_NODES / 128), 256>>>(
        (const float*)p_msg, (const float*)p_h1, DOUT,
        Wap, bap, out, DOUT,
        nullptr, nullptr, nullptr, 0,
        2 * DOUT, 1);
}

// round 9
// speedup vs baseline: 2.6696x; 1.2393x over previous
#include <cuda_runtime.h>
#include <cuda_bf16.h>
#include <math.h>
#include <stdint.h>

// ---------------- Problem constants ----------------
#define N_NODES 12288
#define B_BATCH 64
#define R_REG   36
#define E_EDGES 196608
#define DIN     512
#define DOUT    512
#define PDIM    256
#define DIMG    1024
#define BR      (B_BATCH * R_REG)   // 2304

// ---------------- Scratch (device globals; no allocation allowed) ----------------
__device__ __align__(16) float g_img_proj[BR * PDIM];
__device__ __align__(16) float g_img_fc[BR * DOUT];
__device__ __align__(16) float g_node_proj[N_NODES * PDIM];
__device__ __align__(16) float g_h1[N_NODES * DOUT];
__device__ __align__(16) float g_msg[N_NODES * DOUT];
__device__ int g_deg[N_NODES];
__device__ int g_cursor[N_NODES];
__device__ int g_off[N_NODES + 1];
__device__ int g_csr_src[E_EDGES];
__device__ int g_bdeg[B_BATCH];
__device__ int g_bcur[B_BATCH];
__device__ int g_boff[B_BATCH + 1];
__device__ int g_bnodes[N_NODES];
// Pre-transposed, bf16 hi/lo split weights, [N,K] row-major
__device__ __align__(16) __nv_bfloat16 g_wt_img_hi[768 * 1024];
__device__ __align__(16) __nv_bfloat16 g_wt_img_lo[768 * 1024];
__device__ __align__(16) __nv_bfloat16 g_wt_node_hi[768 * 512];
__device__ __align__(16) __nv_bfloat16 g_wt_node_lo[768 * 512];
__device__ __align__(16) __nv_bfloat16 g_wt_ap_hi[512 * 1024];
__device__ __align__(16) __nv_bfloat16 g_wt_ap_lo[512 * 1024];

// ---------------- helpers ----------------
__device__ __forceinline__ uint32_t smem_u32(const void* p) {
    uint32_t a;
    asm("{ .reg .u64 t; cvta.to.shared.u64 t, %1; cvt.u32.u64 %0, t; }" : "=r"(a) : "l"(p));
    return a;
}
__device__ __forceinline__ uint32_t pack_bf2(float f0, float f1) {
    uint32_t w;
    asm("cvt.rn.bf16x2.f32 %0, %1, %2;" : "=r"(w) : "f"(f1), "f"(f0));
    return w;
}
__device__ __forceinline__ void split2(float f0, float f1, uint32_t& whi, uint32_t& wlo) {
    whi = pack_bf2(f0, f1);
    float h0 = __uint_as_float(whi << 16);
    float h1 = __uint_as_float(whi & 0xffff0000u);
    wlo = pack_bf2(f0 - h0, f1 - h1);
}
__device__ __forceinline__ void mma_bf16(float* c, const uint32_t* a, uint32_t b0, uint32_t b1) {
    asm volatile(
        "mma.sync.aligned.m16n8k16.row.col.f32.bf16.bf16.f32 "
        "{%0,%1,%2,%3}, {%4,%5,%6,%7}, {%8,%9}, {%0,%1,%2,%3};\n"
        : "+f"(c[0]), "+f"(c[1]), "+f"(c[2]), "+f"(c[3])
        : "r"(a[0]), "r"(a[1]), "r"(a[2]), "r"(a[3]), "r"(b0), "r"(b1));
}
__device__ __forceinline__ void ldsm_x4(uint32_t& r0, uint32_t& r1, uint32_t& r2, uint32_t& r3,
                                        uint32_t addr) {
    asm volatile("ldmatrix.sync.aligned.m8n8.x4.shared.b16 {%0,%1,%2,%3}, [%4];"
                 : "=r"(r0), "=r"(r1), "=r"(r2), "=r"(r3) : "r"(addr));
}
#define CP_ASYNC16(dst, src) \
    asm volatile("cp.async.cg.shared.global [%0], [%1], 16;" :: "r"(dst), "l"(src))
#define CP_COMMIT() asm volatile("cp.async.commit_group;" ::: "memory")
#define CP_WAIT0()  asm volatile("cp.async.wait_group 0;" ::: "memory")

// ---------------- Weight transpose + bf16 split: WT[n][k] = W[k][n] ----------------
__global__ void wt_kernel(const float* __restrict__ W, int K, int N,
                          __nv_bfloat16* __restrict__ hi, __nv_bfloat16* __restrict__ lo,
                          int rowoff, int Kd)
{
    __shared__ float tile[32][33];
    const int tx = threadIdx.x, ty = threadIdx.y;   // 32 x 8
    const int n0 = blockIdx.x * 32, k0 = blockIdx.y * 32;
    #pragma unroll
    for (int i = 0; i < 4; i++)
        tile[ty + i * 8][tx] = W[(size_t)(k0 + ty + i * 8) * N + n0 + tx];
    __syncthreads();
    #pragma unroll
    for (int i = 0; i < 4; i++) {
        int n = n0 + ty + i * 8, k = k0 + tx;
        float v = tile[tx][ty + i * 8];
        __nv_bfloat16 hh = __float2bfloat16(v);
        hi[(size_t)(rowoff + n) * Kd + k] = hh;
        lo[(size_t)(rowoff + n) * Kd + k] = __float2bfloat16(v - __bfloat162float(hh));
    }
}

// ================= bf16 3-term mma.sync GEMM, ldmatrix + cp.async =================
// CTA tile 128x128, K-chunk 32, double-buffered smem.
// A fp32 global (optionally concat A|A2 along K at K/2), split hi/lo on the fly.
// B pre-split bf16 [N,K] hi/lo, streamed via cp.async.
// smem layout per stage (pitch 80 B per 32-element bf16 row; conflict-free ldmatrix):
//   A_HI @ 0, A_LO @ 10240, B_HI @ 20480, B_LO @ 30720; stage stride 40960.
#define ST_A_LO 10240
#define ST_B_HI 20480
#define ST_B_LO 30720
#define STAGE   40960
#define GEMM_SMEM (2 * STAGE)

__global__ __launch_bounds__(256, 2) void gemm_ldsm(
    const float* __restrict__ A, const float* __restrict__ A2, int Apitch,
    const __nv_bfloat16* __restrict__ WThi, const __nv_bfloat16* __restrict__ WTlo,
    const float* __restrict__ bias1, float* __restrict__ C1, int N1,
    const float* __restrict__ bias2, float* __restrict__ C2, int N2,
    int K, int do_relu)
{
    extern __shared__ char sm[];
    const uint32_t sb = smem_u32(sm);

    const int tid = threadIdx.x;
    const int lane = tid & 31, warp = tid >> 5;
    const int wm = warp & 3, wn = warp >> 2;
    const int gid = lane >> 2, tig = lane & 3;
    const int bm0 = blockIdx.y * 128;
    const int bn0 = blockIdx.x * 128;

    const float* bias; float* C; int Nc, c0;
    if (bn0 < N1) { C = C1; bias = bias1; Nc = N1; c0 = bn0; }
    else          { C = C2; bias = bias2; Nc = N2; c0 = bn0 - N1; }

    const int T = K >> 5;        // chunks of 32
    const int Khalf = K >> 1;

    const int arow = tid >> 1;          // A/B row within tile (2 threads per row)
    const int half = tid & 1;           // which 16-element half of the 32-wide chunk

    // per-lane ldmatrix row offsets (pitch 80 B)
    const uint32_t a_off = (uint32_t)((lane & 15) * 80 + (lane >> 4) * 16);
    const uint32_t b_off = (uint32_t)(((lane & 7) + ((lane >> 4) << 3)) * 80 + ((lane >> 3) & 1) * 16);

    float c[2][8][4];
    #pragma unroll
    for (int i = 0; i < 2; i++)
        #pragma unroll
        for (int j = 0; j < 8; j++)
            #pragma unroll
            for (int q = 0; q < 4; q++) c[i][j][q] = 0.0f;

    float af[16];

    #define LOAD_A(t_) do {                                                          \
        int kg_ = (t_) * 32 + half * 16;                                             \
        const float* Ab_ = A; int kk_ = kg_;                                         \
        if (A2 != nullptr && kg_ >= Khalf) { Ab_ = A2; kk_ = kg_ - Khalf; }          \
        const float4* pa_ = (const float4*)(Ab_ + (size_t)(bm0 + arow) * Apitch + kk_); \
        float4 v0_ = pa_[0], v1_ = pa_[1], v2_ = pa_[2], v3_ = pa_[3];               \
        af[0]=v0_.x; af[1]=v0_.y; af[2]=v0_.z; af[3]=v0_.w;                          \
        af[4]=v1_.x; af[5]=v1_.y; af[6]=v1_.z; af[7]=v1_.w;                          \
        af[8]=v2_.x; af[9]=v2_.y; af[10]=v2_.z; af[11]=v2_.w;                        \
        af[12]=v3_.x; af[13]=v3_.y; af[14]=v3_.z; af[15]=v3_.w;                      \
    } while (0)

    #define STORE_A(bufi) do {                                                       \
        uint32_t h_[8], l_[8];                                                       \
        _Pragma("unroll")                                                            \
        for (int p_ = 0; p_ < 8; p_++) split2(af[2*p_], af[2*p_+1], h_[p_], l_[p_]); \
        char* d_ = sm + (bufi) * STAGE + arow * 80 + half * 32;                      \
        *(uint4*)(d_)      = make_uint4(h_[0], h_[1], h_[2], h_[3]);                 \
        *(uint4*)(d_ + 16) = make_uint4(h_[4], h_[5], h_[6], h_[7]);                 \
        *(uint4*)(d_ + ST_A_LO)      = make_uint4(l_[0], l_[1], l_[2], l_[3]);       \
        *(uint4*)(d_ + ST_A_LO + 16) = make_uint4(l_[4], l_[5], l_[6], l_[7]);       \
    } while (0)

    #define CPB(t_, bufi) do {                                                       \
        const char* gh_ = (const char*)(WThi + (size_t)(bn0 + arow) * K + (t_) * 32 + half * 16); \
        const char* gl_ = (const char*)(WTlo + (size_t)(bn0 + arow) * K + (t_) * 32 + half * 16); \
        uint32_t dh_ = sb + (bufi) * STAGE + ST_B_HI + arow * 80 + half * 32;        \
        uint32_t dl_ = sb + (bufi) * STAGE + ST_B_LO + arow * 80 + half * 32;        \
        CP_ASYNC16(dh_, gh_);      CP_ASYNC16(dh_ + 16, gh_ + 16);                   \
        CP_ASYNC16(dl_, gl_);      CP_ASYNC16(dl_ + 16, gl_ + 16);                   \
    } while (0)

    // prologue: stage 0
    LOAD_A(0);
    STORE_A(0);
    CPB(0, 0);
    CP_COMMIT();
    CP_WAIT0();
    __syncthreads();

    for (int t = 0; t < T; t++) {
        const int buf = t & 1;
        if (t + 1 < T) {
            LOAD_A(t + 1);
            CPB(t + 1, buf ^ 1);
            CP_COMMIT();
        }

        const uint32_t sstage = sb + buf * STAGE;
        #pragma unroll
        for (int kt = 0; kt < 2; kt++) {
            uint32_t ah[2][4], al[2][4];
            #pragma unroll
            for (int i = 0; i < 2; i++) {
                uint32_t abase = sstage + (uint32_t)((wm * 32 + i * 16) * 80 + kt * 32) + a_off;
                ldsm_x4(ah[i][0], ah[i][1], ah[i][2], ah[i][3], abase);
                ldsm_x4(al[i][0], al[i][1], al[i][2], al[i][3], abase + ST_A_LO);
            }
            #pragma unroll
            for (int j2 = 0; j2 < 4; j2++) {
                uint32_t bh[4], bl[4];
                uint32_t bbase = sstage + ST_B_HI + (uint32_t)((wn * 64 + j2 * 16) * 80 + kt * 32) + b_off;
                ldsm_x4(bh[0], bh[1], bh[2], bh[3], bbase);
                ldsm_x4(bl[0], bl[1], bl[2], bl[3], bbase + (ST_B_LO - ST_B_HI));
                #pragma unroll
                for (int jj = 0; jj < 2; jj++) {
                    #pragma unroll
                    for (int i = 0; i < 2; i++) {
                        float* cc = c[i][j2 * 2 + jj];
                        mma_bf16(cc, ah[i], bh[jj * 2], bh[jj * 2 + 1]);
                        mma_bf16(cc, ah[i], bl[jj * 2], bl[jj * 2 + 1]);
                        mma_bf16(cc, al[i], bh[jj * 2], bh[jj * 2 + 1]);
                    }
                }
            }
        }

        if (t + 1 < T) {
            STORE_A(buf ^ 1);
            CP_WAIT0();
        }
        __syncthreads();
    }
    #undef LOAD_A
    #undef STORE_A
    #undef CPB

    // ---- epilogue: direct global stores ----
    #pragma unroll
    for (int i = 0; i < 2; i++) {
        const int r0 = bm0 + wm * 32 + i * 16 + gid;
        #pragma unroll
        for (int j = 0; j < 8; j++) {
            const int col = c0 + wn * 64 + j * 8 + tig * 2;
            float bv0 = bias ? bias[col]     : 0.0f;
            float bv1 = bias ? bias[col + 1] : 0.0f;
            float v0 = c[i][j][0] + bv0;
            float v1 = c[i][j][1] + bv1;
            float v2 = c[i][j][2] + bv0;
            float v3 = c[i][j][3] + bv1;
            if (do_relu) {
                v0 = fmaxf(v0, 0.0f); v1 = fmaxf(v1, 0.0f);
                v2 = fmaxf(v2, 0.0f); v3 = fmaxf(v3, 0.0f);
            }
            C[(size_t)r0 * Nc + col]           = v0;
            C[(size_t)r0 * Nc + col + 1]       = v1;
            C[(size_t)(r0 + 8) * Nc + col]     = v2;
            C[(size_t)(r0 + 8) * Nc + col + 1] = v3;
        }
    }
}

// ---------------- Batch-grouped attention ----------------
#define ATT_SPLIT 2
#define ATT_SMEM_FLOATS (R_REG * PDIM + R_REG * DOUT + 8 * 40)
#define ATT_SMEM_BYTES  (ATT_SMEM_FLOATS * 4)

__device__ __forceinline__ float htanh(float x) {
    float y;
    asm("tanh.approx.f32 %0, %1;" : "=f"(y) : "f"(x));
    return y;
}

__global__ __launch_bounds__(256) void att2_kernel(
    const float* __restrict__ Wa, const float* __restrict__ ba,
    const float* __restrict__ bim)
{
    extern __shared__ float s_dyn[];
    float* s_ip  = s_dyn;
    float* s_fc  = s_dyn + R_REG * PDIM;
    float* s_att = s_dyn + R_REG * PDIM + R_REG * DOUT;

    const int b = blockIdx.y;
    const int s = blockIdx.x;
    const int tid = threadIdx.x;
    const int lane = tid & 31, warp = tid >> 5;

    {
        const float4* src1 = (const float4*)(g_img_proj + (size_t)b * R_REG * PDIM);
        float4* dst1 = (float4*)s_ip;
        for (int i = tid; i < R_REG * PDIM / 4; i += 256) dst1[i] = src1[i];
        const float4* src2 = (const float4*)(g_img_fc + (size_t)b * R_REG * DOUT);
        float4* dst2 = (float4*)s_fc;
        for (int i = tid; i < R_REG * DOUT / 4; i += 256) dst2[i] = src2[i];
    }
    __syncthreads();

    float wa[8];
    #pragma unroll
    for (int i = 0; i < 8; i++) wa[i] = Wa[lane + 32 * i];
    const float ba0 = ba[0];

    const int start = g_boff[b], end = g_boff[b + 1];
    float* sa = s_att + warp * 40;

    for (int idx = start + s * 8 + warp; idx < end; idx += ATT_SPLIT * 8) {
        const int n = g_bnodes[idx];

        float np[8];
        #pragma unroll
        for (int i = 0; i < 8; i++) np[i] = g_node_proj[(size_t)n * PDIM + lane + 32 * i];

        for (int r = 0; r < R_REG; r++) {
            const float* ip = s_ip + r * PDIM;
            float part = 0.0f;
            #pragma unroll
            for (int i = 0; i < 8; i++)
                part += htanh(np[i] + ip[lane + 32 * i]) * wa[i];
            #pragma unroll
            for (int o = 16; o > 0; o >>= 1) part += __shfl_xor_sync(0xffffffffu, part, o);
            if (lane == 0) sa[r] = part + ba0;
        }
        __syncwarp();

        {
            float v0 = sa[lane];
            float v1 = (lane < 4) ? sa[32 + lane] : -INFINITY;
            float m = fmaxf(v0, v1);
            #pragma unroll
            for (int o = 16; o > 0; o >>= 1) m = fmaxf(m, __shfl_xor_sync(0xffffffffu, m, o));
            float e0 = __expf(v0 - m);
            float e1 = (lane < 4) ? __expf(v1 - m) : 0.0f;
            float ssum = e0 + e1;
            #pragma unroll
            for (int o = 16; o > 0; o >>= 1) ssum += __shfl_xor_sync(0xffffffffu, ssum, o);
            float inv = 1.0f / ssum;
            sa[lane] = e0 * inv;
            if (lane < 4) sa[32 + lane] = e1 * inv;
        }
        __syncwarp();

        float4 acc[4];
        #pragma unroll
        for (int q = 0; q < 4; q++) acc[q] = make_float4(0.f, 0.f, 0.f, 0.f);
        for (int r = 0; r < R_REG; r++) {
            float a = sa[r];
            #pragma unroll
            for (int q = 0; q < 4; q++) {
                float4 v = *(const float4*)&s_fc[r * DOUT + q * 128 + lane * 4];
                acc[q].x += a * v.x; acc[q].y += a * v.y;
                acc[q].z += a * v.z; acc[q].w += a * v.w;
            }
        }
        #pragma unroll
        for (int q = 0; q < 4; q++) {
            float4 bvv = *(const float4*)&bim[q * 128 + lane * 4];
            acc[q].x += bvv.x; acc[q].y += bvv.y; acc[q].z += bvv.z; acc[q].w += bvv.w;
            *(float4*)&g_msg[(size_t)n * DOUT + q * 128 + lane * 4] = acc[q];
        }
        __syncwarp();
    }
}

// ---------------- CSR build ----------------
__global__ void zero_kernel() {
    int i = blockIdx.x * blockDim.x + threadIdx.x;
    if (i < N_NODES) { g_deg[i] = 0; g_cursor[i] = 0; }
    if (i < B_BATCH) { g_bdeg[i] = 0; g_bcur[i] = 0; }
}

__global__ void count_kernel(const int* __restrict__ dst, const int* __restrict__ batch_ids) {
    int e = blockIdx.x * blockDim.x + threadIdx.x;
    if (e < E_EDGES) atomicAdd(&g_deg[dst[e]], 1);
    if (e < N_NODES) atomicAdd(&g_bdeg[batch_ids[e]], 1);
}

__global__ void scan_kernel() {
    __shared__ int s[1024];
    const int tid = threadIdx.x;
    if (tid == 0) {
        int run = 0;
        for (int b = 0; b < B_BATCH; b++) { g_boff[b] = run; run += g_bdeg[b]; }
        g_boff[B_BATCH] = run;
    }
    const int chunk = N_NODES / 1024;
    const int base = tid * chunk;
    int sum = 0;
    #pragma unroll
    for (int i = 0; i < chunk; i++) sum += g_deg[base + i];
    s[tid] = sum;
    __syncthreads();
    for (int ofs = 1; ofs < 1024; ofs <<= 1) {
        int v = (tid >= ofs) ? s[tid - ofs] : 0;
        __syncthreads();
        if (tid >= ofs) s[tid] += v;
        __syncthreads();
    }
    int run = (tid == 0) ? 0 : s[tid - 1];
    #pragma unroll
    for (int i = 0; i < chunk; i++) {
        int idx = base + i;
        g_off[idx] = run;
        run += g_deg[idx];
    }
    if (tid == 0) g_off[N_NODES] = s[1023];
}

__global__ void fill_kernel(const int* __restrict__ src, const int* __restrict__ dst,
                            const int* __restrict__ batch_ids) {
    int e = blockIdx.x * blockDim.x + threadIdx.x;
    if (e < E_EDGES) {
        int d = dst[e];
        int pos = g_off[d] + atomicAdd(&g_cursor[d], 1);
        g_csr_src[pos] = src[e];
    }
    if (e < N_NODES) {
        int b = batch_ids[e];
        int pos = g_boff[b] + atomicAdd(&g_bcur[b], 1);
        g_bnodes[pos] = e;
    }
}

// ---------------- Neighbor sum ----------------
__global__ __launch_bounds__(128) void neigh_kernel() {
    const int n = blockIdx.x;
    const int t = threadIdx.x;
    const int s0 = g_off[n], s1 = g_off[n + 1];
    float4 acc = make_float4(0.f, 0.f, 0.f, 0.f);
    const float4* h1v = (const float4*)g_h1;
    int e = s0;
    #pragma unroll 1
    for (; e + 4 <= s1; e += 4) {
        int a0 = g_csr_src[e + 0], a1 = g_csr_src[e + 1];
        int a2 = g_csr_src[e + 2], a3 = g_csr_src[e + 3];
        float4 v0 = h1v[(size_t)a0 * 128 + t];
        float4 v1 = h1v[(size_t)a1 * 128 + t];
        float4 v2 = h1v[(size_t)a2 * 128 + t];
        float4 v3 = h1v[(size_t)a3 * 128 + t];
        acc.x += v0.x + v1.x + v2.x + v3.x;
        acc.y += v0.y + v1.y + v2.y + v3.y;
        acc.z += v0.z + v1.z + v2.z + v3.z;
        acc.w += v0.w + v1.w + v2.w + v3.w;
    }
    for (; e < s1; e++) {
        int a = g_csr_src[e];
        float4 v = h1v[(size_t)a * 128 + t];
        acc.x += v.x; acc.y += v.y; acc.z += v.z; acc.w += v.w;
    }
    float4* mv = (float4*)g_msg;
    float4 m = mv[(size_t)n * 128 + t];
    m.x += acc.x; m.y += acc.y; m.z += acc.z; m.w += acc.w;
    mv[(size_t)n * 128 + t] = m;
}

// ---------------- Host launcher ----------------
extern "C" void kernel_launch(void* const* d_in, const int* in_sizes, int n_in,
                              void* d_out, int out_size)
{
    const float* h         = (const float*)d_in[0];
    const float* img_feats = (const float*)d_in[1];
    const int*   batch_ids = (const int*)  d_in[2];
    const int*   src       = (const int*)  d_in[3];
    const int*   dst       = (const int*)  d_in[4];
    const float* Wf  = (const float*)d_in[5];
    const float* bf  = (const float*)d_in[6];
    const float* Wi  = (const float*)d_in[7];
    const float* bi  = (const float*)d_in[8];
    const float* Wa  = (const float*)d_in[9];
    const float* ba  = (const float*)d_in[10];
    const float* Wn  = (const float*)d_in[11];
    const float* bn  = (const float*)d_in[12];
    const float* Wim = (const float*)d_in[13];
    const float* bim = (const float*)d_in[14];
    const float* Wap = (const float*)d_in[15];
    const float* bap = (const float*)d_in[16];
    float* out = (float*)d_out;

    void *p_img_proj, *p_img_fc, *p_node_proj, *p_h1, *p_msg;
    void *p_wih, *p_wil, *p_wnh, *p_wnl, *p_wah, *p_wal;
    cudaGetSymbolAddress(&p_img_proj,  g_img_proj);
    cudaGetSymbolAddress(&p_img_fc,    g_img_fc);
    cudaGetSymbolAddress(&p_node_proj, g_node_proj);
    cudaGetSymbolAddress(&p_h1,        g_h1);
    cudaGetSymbolAddress(&p_msg,       g_msg);
    cudaGetSymbolAddress(&p_wih, g_wt_img_hi);
    cudaGetSymbolAddress(&p_wil, g_wt_img_lo);
    cudaGetSymbolAddress(&p_wnh, g_wt_node_hi);
    cudaGetSymbolAddress(&p_wnl, g_wt_node_lo);
    cudaGetSymbolAddress(&p_wah, g_wt_ap_hi);
    cudaGetSymbolAddress(&p_wal, g_wt_ap_lo);

    cudaFuncSetAttribute(att2_kernel,
                         cudaFuncAttributeMaxDynamicSharedMemorySize, ATT_SMEM_BYTES);
    cudaFuncSetAttribute(gemm_ldsm,
                         cudaFuncAttributeMaxDynamicSharedMemorySize, GEMM_SMEM);

    // CSR build
    zero_kernel<<<(N_NODES + 255) / 256, 256>>>();
    count_kernel<<<(E_EDGES + 255) / 256, 256>>>(dst, batch_ids);
    scan_kernel<<<1, 1024>>>();
    fill_kernel<<<(E_EDGES + 255) / 256, 256>>>(src, dst, batch_ids);

    // Weight transpose + split
    dim3 wtb(32, 8);
    wt_kernel<<<dim3(256 / 32, 1024 / 32), wtb>>>(Wi, 1024, 256,
        (__nv_bfloat16*)p_wih, (__nv_bfloat16*)p_wil, 0, 1024);
    wt_kernel<<<dim3(512 / 32, 1024 / 32), wtb>>>(Wim, 1024, 512,
        (__nv_bfloat16*)p_wih, (__nv_bfloat16*)p_wil, 256, 1024);
    wt_kernel<<<dim3(256 / 32, 512 / 32), wtb>>>(Wf, 512, 256,
        (__nv_bfloat16*)p_wnh, (__nv_bfloat16*)p_wnl, 0, 512);
    wt_kernel<<<dim3(512 / 32, 512 / 32), wtb>>>(Wn, 512, 512,
        (__nv_bfloat16*)p_wnh, (__nv_bfloat16*)p_wnl, 256, 512);
    wt_kernel<<<dim3(512 / 32, 1024 / 32), wtb>>>(Wap, 1024, 512,
        (__nv_bfloat16*)p_wah, (__nv_bfloat16*)p_wal, 0, 1024);

    // img: [2304 x 768] = img_feats @ [Wi | Wim], K=1024
    gemm_ldsm<<<dim3(6, BR / 128), 256, GEMM_SMEM>>>(
        img_feats, nullptr, DIMG,
        (const __nv_bfloat16*)p_wih, (const __nv_bfloat16*)p_wil,
        bi, (float*)p_img_proj, PDIM,
        nullptr, (float*)p_img_fc, DOUT,
        DIMG, 0);

    // node: [12288 x 768] = h @ [Wf | Wn], K=512
    gemm_ldsm<<<dim3(6, N_NODES / 128), 256, GEMM_SMEM>>>(
        h, nullptr, DIN,
        (const __nv_bfloat16*)p_wnh, (const __nv_bfloat16*)p_wnl,
        bf, (float*)p_node_proj, PDIM,
        bn, (float*)p_h1, DOUT,
        DIN, 0);

    // g_msg = bim + att @ img_fc
    att2_kernel<<<dim3(ATT_SPLIT, B_BATCH), 256, ATT_SMEM_BYTES>>>(Wa, ba, bim);

    // g_msg += segment_sum(h1[src], dst)
    neigh_kernel<<<N_NODES, 128>>>();

    // out = relu([msg | h1] @ Wap + bap), K=1024 concat split at 512
    gemm_ldsm<<<dim3(4, N_NODES / 128), 256, GEMM_SMEM>>>(
        (const float*)p_msg, (const float*)p_h1, DOUT,
        (const __nv_bfloat16*)p_wah, (const __nv_bfloat16*)p_wal,
        bap, out, DOUT,
        nullptr, nullptr, 0,
        2 * DOUT, 1);
}

// round 10
// speedup vs baseline: 2.7235x; 1.0202x over previous
#include <cuda_runtime.h>
#include <cuda_bf16.h>
#include <math.h>
#include <stdint.h>

// ---------------- Problem constants ----------------
#define N_NODES 12288
#define B_BATCH 64
#define R_REG   36
#define E_EDGES 196608
#define DIN     512
#define DOUT    512
#define PDIM    256
#define DIMG    1024
#define BR      (B_BATCH * R_REG)   // 2304

// ---------------- Scratch (device globals; no allocation allowed) ----------------
__device__ __align__(16) float g_img_proj[BR * PDIM];
__device__ __align__(16) float g_img_fc[BR * DOUT];
__device__ __align__(16) float g_node_proj[N_NODES * PDIM];
__device__ __align__(16) float g_h1[N_NODES * DOUT];
__device__ __align__(16) float g_msg[N_NODES * DOUT];
__device__ int g_deg[N_NODES];
__device__ int g_cursor[N_NODES];
__device__ int g_off[N_NODES + 1];
__device__ int g_csr_src[E_EDGES];
__device__ int g_bdeg[B_BATCH];
__device__ int g_bcur[B_BATCH];
__device__ int g_boff[B_BATCH + 1];
__device__ int g_bnodes[N_NODES];
// Pre-transposed, bf16 hi/lo split weights, [N,K] row-major
__device__ __align__(16) __nv_bfloat16 g_wt_img_hi[768 * 1024];
__device__ __align__(16) __nv_bfloat16 g_wt_img_lo[768 * 1024];
__device__ __align__(16) __nv_bfloat16 g_wt_node_hi[768 * 512];
__device__ __align__(16) __nv_bfloat16 g_wt_node_lo[768 * 512];
__device__ __align__(16) __nv_bfloat16 g_wt_ap_hi[512 * 1024];
__device__ __align__(16) __nv_bfloat16 g_wt_ap_lo[512 * 1024];
// Pre-split activations, bf16 hi/lo, row-major
__device__ __align__(16) __nv_bfloat16 g_as_img_hi[BR * DIMG];
__device__ __align__(16) __nv_bfloat16 g_as_img_lo[BR * DIMG];
__device__ __align__(16) __nv_bfloat16 g_as_node_hi[N_NODES * DIN];
__device__ __align__(16) __nv_bfloat16 g_as_node_lo[N_NODES * DIN];
__device__ __align__(16) __nv_bfloat16 g_as_ap_hi[N_NODES * 1024];   // [msg | h1]
__device__ __align__(16) __nv_bfloat16 g_as_ap_lo[N_NODES * 1024];

// ---------------- helpers ----------------
__device__ __forceinline__ uint32_t smem_u32(const void* p) {
    uint32_t a;
    asm("{ .reg .u64 t; cvta.to.shared.u64 t, %1; cvt.u32.u64 %0, t; }" : "=r"(a) : "l"(p));
    return a;
}
__device__ __forceinline__ uint32_t pack_bf2(float f0, float f1) {
    uint32_t w;
    asm("cvt.rn.bf16x2.f32 %0, %1, %2;" : "=r"(w) : "f"(f1), "f"(f0));
    return w;
}
__device__ __forceinline__ void split2(float f0, float f1, uint32_t& whi, uint32_t& wlo) {
    whi = pack_bf2(f0, f1);
    float h0 = __uint_as_float(whi << 16);
    float h1 = __uint_as_float(whi & 0xffff0000u);
    wlo = pack_bf2(f0 - h0, f1 - h1);
}
__device__ __forceinline__ void mma_bf16(float* c, const uint32_t* a, uint32_t b0, uint32_t b1) {
    asm volatile(
        "mma.sync.aligned.m16n8k16.row.col.f32.bf16.bf16.f32 "
        "{%0,%1,%2,%3}, {%4,%5,%6,%7}, {%8,%9}, {%0,%1,%2,%3};\n"
        : "+f"(c[0]), "+f"(c[1]), "+f"(c[2]), "+f"(c[3])
        : "r"(a[0]), "r"(a[1]), "r"(a[2]), "r"(a[3]), "r"(b0), "r"(b1));
}
__device__ __forceinline__ void ldsm_x4(uint32_t& r0, uint32_t& r1, uint32_t& r2, uint32_t& r3,
                                        uint32_t addr) {
    asm volatile("ldmatrix.sync.aligned.m8n8.x4.shared.b16 {%0,%1,%2,%3}, [%4];"
                 : "=r"(r0), "=r"(r1), "=r"(r2), "=r"(r3) : "r"(addr));
}
#define CP_ASYNC16(dst, src) \
    asm volatile("cp.async.cg.shared.global [%0], [%1], 16;" :: "r"(dst), "l"(src))
#define CP_COMMIT() asm volatile("cp.async.commit_group;" ::: "memory")
#define CP_WAIT1()  asm volatile("cp.async.wait_group 1;" ::: "memory")
#define CP_WAIT0()  asm volatile("cp.async.wait_group 0;" ::: "memory")

// ---------------- Weight transpose + bf16 split: WT[n][k] = W[k][n] ----------------
__global__ void wt_kernel(const float* __restrict__ W, int K, int N,
                          __nv_bfloat16* __restrict__ hi, __nv_bfloat16* __restrict__ lo,
                          int rowoff, int Kd)
{
    __shared__ float tile[32][33];
    const int tx = threadIdx.x, ty = threadIdx.y;   // 32 x 8
    const int n0 = blockIdx.x * 32, k0 = blockIdx.y * 32;
    #pragma unroll
    for (int i = 0; i < 4; i++)
        tile[ty + i * 8][tx] = W[(size_t)(k0 + ty + i * 8) * N + n0 + tx];
    __syncthreads();
    #pragma unroll
    for (int i = 0; i < 4; i++) {
        int n = n0 + ty + i * 8, k = k0 + tx;
        float v = tile[tx][ty + i * 8];
        __nv_bfloat16 hh = __float2bfloat16(v);
        hi[(size_t)(rowoff + n) * Kd + k] = hh;
        lo[(size_t)(rowoff + n) * Kd + k] = __float2bfloat16(v - __bfloat162float(hh));
    }
}

// ---------------- Activation split: fp32 -> bf16 hi/lo ----------------
__global__ void split_kernel(const float4* __restrict__ in, int total4, int shift,
                             int pitch, int coloff,
                             __nv_bfloat16* __restrict__ hi, __nv_bfloat16* __restrict__ lo)
{
    int i = blockIdx.x * blockDim.x + threadIdx.x;
    if (i >= total4) return;
    int row = i >> shift;
    int c4 = i & ((1 << shift) - 1);
    float4 v = in[i];
    uint32_t h0, l0, h1, l1;
    split2(v.x, v.y, h0, l0);
    split2(v.z, v.w, h1, l1);
    size_t o = (size_t)row * pitch + coloff + c4 * 4;
    *(uint2*)(hi + o) = make_uint2(h0, h1);
    *(uint2*)(lo + o) = make_uint2(l0, l1);
}

// ================= bf16 3-term mma.sync GEMM v2 =================
// 512 threads, CTA tile 128x128, K-chunk 32, 3-stage cp.async pipeline.
// A and B both pre-split bf16 [*, K] row-major; XOR-swizzled 64B-row smem.
// Two param sets selected by blockIdx.y (fused small+large GEMMs).
// Column-block output select: bn0 < N1 -> C1, else C2.

struct GArg {
    const __nv_bfloat16* Ahi; const __nv_bfloat16* Alo; int Ap;
    const __nv_bfloat16* Bhi; const __nv_bfloat16* Blo; int K;
    const float* bias1; float* C1; int N1;
    const float* bias2; float* C2; int N2;
    int relu;
};

#define OFF_AL 8192
#define OFF_BH 16384
#define OFF_BL 24576
#define STAGE  32768
#define NS 3
#define GEMM_SMEM (NS * STAGE)
#define SWZ(r, c) ((((c) ^ (((r) >> 1) & 3))) << 4)

__global__ __launch_bounds__(512, 1) void gemm2(GArg ga, GArg gb, int ysplit) {
    extern __shared__ char sm[];
    const uint32_t sb = smem_u32(sm);
    const int tid = threadIdx.x;
    const int lane = tid & 31, warp = tid >> 5;
    const int wm = warp & 3, wn = warp >> 2;
    const int gid = lane >> 2, tig = lane & 3;

    const bool first = ((int)blockIdx.y < ysplit);
    const GArg g = first ? ga : gb;
    const int bm0 = (first ? (int)blockIdx.y : (int)blockIdx.y - ysplit) * 128;
    const int bn0 = (int)blockIdx.x * 128;

    const float* bias; float* C; int Nc, c0;
    if (bn0 < g.N1) { C = g.C1; bias = g.bias1; Nc = g.N1; c0 = bn0; }
    else            { C = g.C2; bias = g.bias2; Nc = g.N2; c0 = bn0 - g.N1; }

    const int T = g.K >> 5;
    const int lrow = tid >> 2;     // 0..127
    const int lc   = tid & 3;      // 16B column within 64B slice

    const char* gAh = (const char*)(g.Ahi + (size_t)(bm0 + lrow) * g.Ap) + lc * 16;
    const char* gAl = (const char*)(g.Alo + (size_t)(bm0 + lrow) * g.Ap) + lc * 16;
    const char* gBh = (const char*)(g.Bhi + (size_t)(bn0 + lrow) * g.K) + lc * 16;
    const char* gBl = (const char*)(g.Blo + (size_t)(bn0 + lrow) * g.K) + lc * 16;
    const uint32_t dstoff = (uint32_t)(lrow * 64 + SWZ(lrow, lc));

    #define ISSUE(t_, buf_) do {                                       \
        uint32_t d_ = sb + (buf_) * STAGE + dstoff;                    \
        size_t go_ = (size_t)(t_) * 64;                                \
        CP_ASYNC16(d_,          gAh + go_);                            \
        CP_ASYNC16(d_ + OFF_AL, gAl + go_);                            \
        CP_ASYNC16(d_ + OFF_BH, gBh + go_);                            \
        CP_ASYNC16(d_ + OFF_BL, gBl + go_);                            \
    } while (0)

    float c4[2][4][4];
    #pragma unroll
    for (int i = 0; i < 2; i++)
        #pragma unroll
        for (int j = 0; j < 4; j++)
            #pragma unroll
            for (int q = 0; q < 4; q++) c4[i][j][q] = 0.0f;

    // prologue
    ISSUE(0, 0); CP_COMMIT();
    if (T > 1) { ISSUE(1, 1); CP_COMMIT(); }

    for (int t = 0; t < T; t++) {
        if (t < T - 1) CP_WAIT1(); else CP_WAIT0();
        __syncthreads();
        if (t + 2 < T) { ISSUE(t + 2, (t + 2) % NS); CP_COMMIT(); }

        const uint32_t ss = sb + (uint32_t)(t % NS) * STAGE;
        #pragma unroll
        for (int kt = 0; kt < 2; kt++) {
            uint32_t ah[2][4], al[2][4];
            #pragma unroll
            for (int i = 0; i < 2; i++) {
                int ra = wm * 32 + i * 16 + (lane & 15);
                int ca = kt * 2 + (lane >> 4);
                uint32_t aa = ss + (uint32_t)(ra * 64 + SWZ(ra, ca));
                ldsm_x4(ah[i][0], ah[i][1], ah[i][2], ah[i][3], aa);
                ldsm_x4(al[i][0], al[i][1], al[i][2], al[i][3], aa + OFF_AL);
            }
            #pragma unroll
            for (int j2 = 0; j2 < 2; j2++) {
                int rb = wn * 32 + j2 * 16 + (lane & 7) + ((lane >> 4) << 3);
                int cb = kt * 2 + ((lane >> 3) & 1);
                uint32_t ba = ss + OFF_BH + (uint32_t)(rb * 64 + SWZ(rb, cb));
                uint32_t bh[4], bl[4];
                ldsm_x4(bh[0], bh[1], bh[2], bh[3], ba);
                ldsm_x4(bl[0], bl[1], bl[2], bl[3], ba + (OFF_BL - OFF_BH));
                #pragma unroll
                for (int jj = 0; jj < 2; jj++) {
                    #pragma unroll
                    for (int i = 0; i < 2; i++) {
                        float* cc = c4[i][j2 * 2 + jj];
                        mma_bf16(cc, ah[i], bh[jj * 2], bh[jj * 2 + 1]);
                        mma_bf16(cc, ah[i], bl[jj * 2], bl[jj * 2 + 1]);
                        mma_bf16(cc, al[i], bh[jj * 2], bh[jj * 2 + 1]);
                    }
                }
            }
        }
    }
    #undef ISSUE

    // ---- epilogue ----
    #pragma unroll
    for (int i = 0; i < 2; i++) {
        const int r0 = bm0 + wm * 32 + i * 16 + gid;
        #pragma unroll
        for (int j = 0; j < 4; j++) {
            const int col = c0 + wn * 32 + j * 8 + tig * 2;
            float bv0 = bias ? bias[col]     : 0.0f;
            float bv1 = bias ? bias[col + 1] : 0.0f;
            float v0 = c4[i][j][0] + bv0;
            float v1 = c4[i][j][1] + bv1;
            float v2 = c4[i][j][2] + bv0;
            float v3 = c4[i][j][3] + bv1;
            if (g.relu) {
                v0 = fmaxf(v0, 0.0f); v1 = fmaxf(v1, 0.0f);
                v2 = fmaxf(v2, 0.0f); v3 = fmaxf(v3, 0.0f);
            }
            C[(size_t)r0 * Nc + col]           = v0;
            C[(size_t)r0 * Nc + col + 1]       = v1;
            C[(size_t)(r0 + 8) * Nc + col]     = v2;
            C[(size_t)(r0 + 8) * Nc + col + 1] = v3;
        }
    }
}

// ---------------- Batch-grouped attention ----------------
#define ATT_SPLIT 2
#define ATT_SMEM_FLOATS (R_REG * PDIM + R_REG * DOUT + 8 * 40)
#define ATT_SMEM_BYTES  (ATT_SMEM_FLOATS * 4)

__device__ __forceinline__ float htanh(float x) {
    float y;
    asm("tanh.approx.f32 %0, %1;" : "=f"(y) : "f"(x));
    return y;
}

__global__ __launch_bounds__(256) void att2_kernel(
    const float* __restrict__ Wa, const float* __restrict__ ba,
    const float* __restrict__ bim)
{
    extern __shared__ float s_dyn[];
    float* s_ip  = s_dyn;
    float* s_fc  = s_dyn + R_REG * PDIM;
    float* s_att = s_dyn + R_REG * PDIM + R_REG * DOUT;

    const int b = blockIdx.y;
    const int s = blockIdx.x;
    const int tid = threadIdx.x;
    const int lane = tid & 31, warp = tid >> 5;

    {
        const float4* src1 = (const float4*)(g_img_proj + (size_t)b * R_REG * PDIM);
        float4* dst1 = (float4*)s_ip;
        for (int i = tid; i < R_REG * PDIM / 4; i += 256) dst1[i] = src1[i];
        const float4* src2 = (const float4*)(g_img_fc + (size_t)b * R_REG * DOUT);
        float4* dst2 = (float4*)s_fc;
        for (int i = tid; i < R_REG * DOUT / 4; i += 256) dst2[i] = src2[i];
    }
    __syncthreads();

    float wa[8];
    #pragma unroll
    for (int i = 0; i < 8; i++) wa[i] = Wa[lane + 32 * i];
    const float ba0 = ba[0];

    const int start = g_boff[b], end = g_boff[b + 1];
    float* sa = s_att + warp * 40;

    for (int idx = start + s * 8 + warp; idx < end; idx += ATT_SPLIT * 8) {
        const int n = g_bnodes[idx];

        float np[8];
        #pragma unroll
        for (int i = 0; i < 8; i++) np[i] = g_node_proj[(size_t)n * PDIM + lane + 32 * i];

        for (int r = 0; r < R_REG; r++) {
            const float* ip = s_ip + r * PDIM;
            float part = 0.0f;
            #pragma unroll
            for (int i = 0; i < 8; i++)
                part += htanh(np[i] + ip[lane + 32 * i]) * wa[i];
            #pragma unroll
            for (int o = 16; o > 0; o >>= 1) part += __shfl_xor_sync(0xffffffffu, part, o);
            if (lane == 0) sa[r] = part + ba0;
        }
        __syncwarp();

        {
            float v0 = sa[lane];
            float v1 = (lane < 4) ? sa[32 + lane] : -INFINITY;
            float m = fmaxf(v0, v1);
            #pragma unroll
            for (int o = 16; o > 0; o >>= 1) m = fmaxf(m, __shfl_xor_sync(0xffffffffu, m, o));
            float e0 = __expf(v0 - m);
            float e1 = (lane < 4) ? __expf(v1 - m) : 0.0f;
            float ssum = e0 + e1;
            #pragma unroll
            for (int o = 16; o > 0; o >>= 1) ssum += __shfl_xor_sync(0xffffffffu, ssum, o);
            float inv = 1.0f / ssum;
            sa[lane] = e0 * inv;
            if (lane < 4) sa[32 + lane] = e1 * inv;
        }
        __syncwarp();

        float4 acc[4];
        #pragma unroll
        for (int q = 0; q < 4; q++) acc[q] = make_float4(0.f, 0.f, 0.f, 0.f);
        for (int r = 0; r < R_REG; r++) {
            float a = sa[r];
            #pragma unroll
            for (int q = 0; q < 4; q++) {
                float4 v = *(const float4*)&s_fc[r * DOUT + q * 128 + lane * 4];
                acc[q].x += a * v.x; acc[q].y += a * v.y;
                acc[q].z += a * v.z; acc[q].w += a * v.w;
            }
        }
        #pragma unroll
        for (int q = 0; q < 4; q++) {
            float4 bvv = *(const float4*)&bim[q * 128 + lane * 4];
            acc[q].x += bvv.x; acc[q].y += bvv.y; acc[q].z += bvv.z; acc[q].w += bvv.w;
            *(float4*)&g_msg[(size_t)n * DOUT + q * 128 + lane * 4] = acc[q];
        }
        __syncwarp();
    }
}

// ---------------- CSR build ----------------
__global__ void zero_kernel() {
    int i = blockIdx.x * blockDim.x + threadIdx.x;
    if (i < N_NODES) { g_deg[i] = 0; g_cursor[i] = 0; }
    if (i < B_BATCH) { g_bdeg[i] = 0; g_bcur[i] = 0; }
}

__global__ void count_kernel(const int* __restrict__ dst, const int* __restrict__ batch_ids) {
    int e = blockIdx.x * blockDim.x + threadIdx.x;
    if (e < E_EDGES) atomicAdd(&g_deg[dst[e]], 1);
    if (e < N_NODES) atomicAdd(&g_bdeg[batch_ids[e]], 1);
}

__global__ void scan_kernel() {
    __shared__ int s[1024];
    const int tid = threadIdx.x;
    if (tid == 0) {
        int run = 0;
        for (int b = 0; b < B_BATCH; b++) { g_boff[b] = run; run += g_bdeg[b]; }
        g_boff[B_BATCH] = run;
    }
    const int chunk = N_NODES / 1024;
    const int base = tid * chunk;
    int sum = 0;
    #pragma unroll
    for (int i = 0; i < chunk; i++) sum += g_deg[base + i];
    s[tid] = sum;
    __syncthreads();
    for (int ofs = 1; ofs < 1024; ofs <<= 1) {
        int v = (tid >= ofs) ? s[tid - ofs] : 0;
        __syncthreads();
        if (tid >= ofs) s[tid] += v;
        __syncthreads();
    }
    int run = (tid == 0) ? 0 : s[tid - 1];
    #pragma unroll
    for (int i = 0; i < chunk; i++) {
        int idx = base + i;
        g_off[idx] = run;
        run += g_deg[idx];
    }
    if (tid == 0) g_off[N_NODES] = s[1023];
}

__global__ void fill_kernel(const int* __restrict__ src, const int* __restrict__ dst,
                            const int* __restrict__ batch_ids) {
    int e = blockIdx.x * blockDim.x + threadIdx.x;
    if (e < E_EDGES) {
        int d = dst[e];
        int pos = g_off[d] + atomicAdd(&g_cursor[d], 1);
        g_csr_src[pos] = src[e];
    }
    if (e < N_NODES) {
        int b = batch_ids[e];
        int pos = g_boff[b] + atomicAdd(&g_bcur[b], 1);
        g_bnodes[pos] = e;
    }
}

// ---------------- Neighbor sum + fused bf16 split of msg ----------------
// msg_final[n] = g_msg[n] + sum h1[src]; written directly as split bf16 into
// g_as_ap (columns 0..511).
__global__ __launch_bounds__(128) void neigh_kernel() {
    const int n = blockIdx.x;
    const int t = threadIdx.x;
    const int s0 = g_off[n], s1 = g_off[n + 1];
    float4 acc = make_float4(0.f, 0.f, 0.f, 0.f);
    const float4* h1v = (const float4*)g_h1;
    int e = s0;
    #pragma unroll 1
    for (; e + 4 <= s1; e += 4) {
        int a0 = g_csr_src[e + 0], a1 = g_csr_src[e + 1];
        int a2 = g_csr_src[e + 2], a3 = g_csr_src[e + 3];
        float4 v0 = h1v[(size_t)a0 * 128 + t];
        float4 v1 = h1v[(size_t)a1 * 128 + t];
        float4 v2 = h1v[(size_t)a2 * 128 + t];
        float4 v3 = h1v[(size_t)a3 * 128 + t];
        acc.x += v0.x + v1.x + v2.x + v3.x;
        acc.y += v0.y + v1.y + v2.y + v3.y;
        acc.z += v0.z + v1.z + v2.z + v3.z;
        acc.w += v0.w + v1.w + v2.w + v3.w;
    }
    for (; e < s1; e++) {
        int a = g_csr_src[e];
        float4 v = h1v[(size_t)a * 128 + t];
        acc.x += v.x; acc.y += v.y; acc.z += v.z; acc.w += v.w;
    }
    float4 m = ((const float4*)g_msg)[(size_t)n * 128 + t];
    m.x += acc.x; m.y += acc.y; m.z += acc.z; m.w += acc.w;
    uint32_t h0, l0, h1_, l1;
    split2(m.x, m.y, h0, l0);
    split2(m.z, m.w, h1_, l1);
    size_t o = (size_t)n * 1024 + t * 4;
    *(uint2*)(g_as_ap_hi + o) = make_uint2(h0, h1_);
    *(uint2*)(g_as_ap_lo + o) = make_uint2(l0, l1);
}

// ---------------- Host launcher ----------------
extern "C" void kernel_launch(void* const* d_in, const int* in_sizes, int n_in,
                              void* d_out, int out_size)
{
    const float* h         = (const float*)d_in[0];
    const float* img_feats = (const float*)d_in[1];
    const int*   batch_ids = (const int*)  d_in[2];
    const int*   src       = (const int*)  d_in[3];
    const int*   dst       = (const int*)  d_in[4];
    const float* Wf  = (const float*)d_in[5];
    const float* bf  = (const float*)d_in[6];
    const float* Wi  = (const float*)d_in[7];
    const float* bi  = (const float*)d_in[8];
    const float* Wa  = (const float*)d_in[9];
    const float* ba  = (const float*)d_in[10];
    const float* Wn  = (const float*)d_in[11];
    const float* bn  = (const float*)d_in[12];
    const float* Wim = (const float*)d_in[13];
    const float* bim = (const float*)d_in[14];
    const float* Wap = (const float*)d_in[15];
    const float* bap = (const float*)d_in[16];
    float* out = (float*)d_out;

    void *p_img_proj, *p_img_fc, *p_node_proj, *p_h1;
    void *p_wih, *p_wil, *p_wnh, *p_wnl, *p_wah, *p_wal;
    void *p_aih, *p_ail, *p_anh, *p_anl, *p_aph, *p_apl;
    cudaGetSymbolAddress(&p_img_proj,  g_img_proj);
    cudaGetSymbolAddress(&p_img_fc,    g_img_fc);
    cudaGetSymbolAddress(&p_node_proj, g_node_proj);
    cudaGetSymbolAddress(&p_h1,        g_h1);
    cudaGetSymbolAddress(&p_wih, g_wt_img_hi);
    cudaGetSymbolAddress(&p_wil, g_wt_img_lo);
    cudaGetSymbolAddress(&p_wnh, g_wt_node_hi);
    cudaGetSymbolAddress(&p_wnl, g_wt_node_lo);
    cudaGetSymbolAddress(&p_wah, g_wt_ap_hi);
    cudaGetSymbolAddress(&p_wal, g_wt_ap_lo);
    cudaGetSymbolAddress(&p_aih, g_as_img_hi);
    cudaGetSymbolAddress(&p_ail, g_as_img_lo);
    cudaGetSymbolAddress(&p_anh, g_as_node_hi);
    cudaGetSymbolAddress(&p_anl, g_as_node_lo);
    cudaGetSymbolAddress(&p_aph, g_as_ap_hi);
    cudaGetSymbolAddress(&p_apl, g_as_ap_lo);

    cudaFuncSetAttribute(att2_kernel,
                         cudaFuncAttributeMaxDynamicSharedMemorySize, ATT_SMEM_BYTES);
    cudaFuncSetAttribute(gemm2,
                         cudaFuncAttributeMaxDynamicSharedMemorySize, GEMM_SMEM);

    // CSR build
    zero_kernel<<<(N_NODES + 255) / 256, 256>>>();
    count_kernel<<<(E_EDGES + 255) / 256, 256>>>(dst, batch_ids);
    scan_kernel<<<1, 1024>>>();
    fill_kernel<<<(E_EDGES + 255) / 256, 256>>>(src, dst, batch_ids);

    // Weight transpose + split
    dim3 wtb(32, 8);
    wt_kernel<<<dim3(256 / 32, 1024 / 32), wtb>>>(Wi, 1024, 256,
        (__nv_bfloat16*)p_wih, (__nv_bfloat16*)p_wil, 0, 1024);
    wt_kernel<<<dim3(512 / 32, 1024 / 32), wtb>>>(Wim, 1024, 512,
        (__nv_bfloat16*)p_wih, (__nv_bfloat16*)p_wil, 256, 1024);
    wt_kernel<<<dim3(256 / 32, 512 / 32), wtb>>>(Wf, 512, 256,
        (__nv_bfloat16*)p_wnh, (__nv_bfloat16*)p_wnl, 0, 512);
    wt_kernel<<<dim3(512 / 32, 512 / 32), wtb>>>(Wn, 512, 512,
        (__nv_bfloat16*)p_wnh, (__nv_bfloat16*)p_wnl, 256, 512);
    wt_kernel<<<dim3(512 / 32, 1024 / 32), wtb>>>(Wap, 1024, 512,
        (__nv_bfloat16*)p_wah, (__nv_bfloat16*)p_wal, 0, 1024);

    // Activation splits
    split_kernel<<<(BR * DIMG / 4 + 255) / 256, 256>>>(
        (const float4*)img_feats, BR * DIMG / 4, 8, 1024, 0,
        (__nv_bfloat16*)p_aih, (__nv_bfloat16*)p_ail);
    split_kernel<<<(N_NODES * DIN / 4 + 255) / 256, 256>>>(
        (const float4*)h, N_NODES * DIN / 4, 7, 512, 0,
        (__nv_bfloat16*)p_anh, (__nv_bfloat16*)p_anl);

    // Fused GEMM: node [12288 x 768] (y 0..95) + img [2304 x 768] (y 96..113)
    GArg gnode, gimg, gap;
    gnode.Ahi = (const __nv_bfloat16*)p_anh; gnode.Alo = (const __nv_bfloat16*)p_anl;
    gnode.Ap = DIN;
    gnode.Bhi = (const __nv_bfloat16*)p_wnh; gnode.Blo = (const __nv_bfloat16*)p_wnl;
    gnode.K = DIN;
    gnode.bias1 = bf; gnode.C1 = (float*)p_node_proj; gnode.N1 = PDIM;
    gnode.bias2 = bn; gnode.C2 = (float*)p_h1;        gnode.N2 = DOUT;
    gnode.relu = 0;

    gimg.Ahi = (const __nv_bfloat16*)p_aih; gimg.Alo = (const __nv_bfloat16*)p_ail;
    gimg.Ap = DIMG;
    gimg.Bhi = (const __nv_bfloat16*)p_wih; gimg.Blo = (const __nv_bfloat16*)p_wil;
    gimg.K = DIMG;
    gimg.bias1 = bi;      gimg.C1 = (float*)p_img_proj; gimg.N1 = PDIM;
    gimg.bias2 = nullptr; gimg.C2 = (float*)p_img_fc;   gimg.N2 = DOUT;
    gimg.relu = 0;

    gemm2<<<dim3(6, 114), 512, GEMM_SMEM>>>(gnode, gimg, 96);

    // h1 split into ap buffer columns 512..1023
    split_kernel<<<(N_NODES * DOUT / 4 + 255) / 256, 256>>>(
        (const float4*)p_h1, N_NODES * DOUT / 4, 7, 1024, 512,
        (__nv_bfloat16*)p_aph, (__nv_bfloat16*)p_apl);

    // g_msg = bim + att @ img_fc
    att2_kernel<<<dim3(ATT_SPLIT, B_BATCH), 256, ATT_SMEM_BYTES>>>(Wa, ba, bim);

    // msg += segment_sum(h1[src], dst); split into ap columns 0..511
    neigh_kernel<<<N_NODES, 128>>>();

    // out = relu([msg | h1] @ Wap + bap)
    gap.Ahi = (const __nv_bfloat16*)p_aph; gap.Alo = (const __nv_bfloat16*)p_apl;
    gap.Ap = 1024;
    gap.Bhi = (const __nv_bfloat16*)p_wah; gap.Blo = (const __nv_bfloat16*)p_wal;
    gap.K = 1024;
    gap.bias1 = bap; gap.C1 = out; gap.N1 = DOUT;
    gap.bias2 = nullptr; gap.C2 = nullptr; gap.N2 = 0;
    gap.relu = 1;

    gemm2<<<dim3(4, 96), 512, GEMM_SMEM>>>(gap, gap, 96);
}